// round 2
// baseline (speedup 1.0000x reference)
#include <cuda_runtime.h>

// ---------------------------------------------------------------------------
// RelativeSelfAttention: B=4, L=1024, E=1024, H=16, D=64, K=64 (129 PE rows)
//
// Stage 1: qkv = q @ W3^T + b3, scattered to per-head Q (scaled 1/8), K, V
// Stage 2: bias_r[bh,i,r] = Q_s[bh,i,:] . rel_pe[r,:]   (r in [0,129))
// Stage 3: flash attention per (bh, 64-row tile): S = Q_s K^T + gather(bias_r),
//          online softmax, O = P V
// Stage 4: out = X @ out_w^T + out_b with X gathered from (b,h,l,d)->(b,l,e)
// ---------------------------------------------------------------------------

#define NBH   64          // B*H
#define LSEQ  1024
#define DH    64
#define BSTR  132         // padded bias_r row stride (129 used)

__device__ float g_Q[NBH * LSEQ * DH];
__device__ float g_K[NBH * LSEQ * DH];
__device__ float g_V[NBH * LSEQ * DH];
__device__ float g_O[NBH * LSEQ * DH];
__device__ float g_bias[NBH * LSEQ * BSTR];

// ---------------------------------------------------------------------------
// Stage 1: QKV GEMM.  C[m,n] = sum_k q[m,k] * W[n,k] + b[n]
// M=4096, N=3072, K=1024. 64x64 tile, BK=16, 256 threads, 4x4 microtile.
// Epilogue scatters into g_Q (x0.125) / g_K / g_V in (b,h,l,d) layout.
// ---------------------------------------------------------------------------
__global__ __launch_bounds__(256) void qkv_gemm(
    const float* __restrict__ A,     // [4096,1024]
    const float* __restrict__ W,     // [3072,1024]
    const float* __restrict__ bias)  // [3072]
{
    __shared__ float As[16][64];   // [k][m]
    __shared__ float Bs[16][64];   // [k][n]
    const int m0 = blockIdx.y << 6;
    const int n0 = blockIdx.x << 6;
    const int tid = threadIdx.x;
    const int tx = tid & 15, ty = tid >> 4;
    const int lr = tid >> 2;
    const int lc = (tid & 3) << 2;

    float acc[4][4] = {};
    const float* Ap = A + (m0 + lr) * 1024 + lc;
    const float* Wp = W + (n0 + lr) * 1024 + lc;

    for (int k0 = 0; k0 < 1024; k0 += 16) {
        float4 a = *(const float4*)(Ap + k0);
        float4 w = *(const float4*)(Wp + k0);
        __syncthreads();
        As[lc + 0][lr] = a.x; As[lc + 1][lr] = a.y;
        As[lc + 2][lr] = a.z; As[lc + 3][lr] = a.w;
        Bs[lc + 0][lr] = w.x; Bs[lc + 1][lr] = w.y;
        Bs[lc + 2][lr] = w.z; Bs[lc + 3][lr] = w.w;
        __syncthreads();
        #pragma unroll
        for (int k = 0; k < 16; ++k) {
            float4 av = *(const float4*)&As[k][ty << 2];
            float4 bv = *(const float4*)&Bs[k][tx << 2];
            float am[4] = {av.x, av.y, av.z, av.w};
            float bm[4] = {bv.x, bv.y, bv.z, bv.w};
            #pragma unroll
            for (int i = 0; i < 4; ++i)
                #pragma unroll
                for (int j = 0; j < 4; ++j)
                    acc[i][j] = fmaf(am[i], bm[j], acc[i][j]);
        }
    }

    // epilogue: whole tile belongs to one of {Q,K,V} and one head (N tile = 64)
    const int part = n0 >> 10;
    const int h = (n0 & 1023) >> 6;
    float* dst = part == 0 ? g_Q : (part == 1 ? g_K : g_V);
    const float scale = (part == 0) ? 0.125f : 1.0f;   // 1/sqrt(64)
    const int nb = n0 + (tx << 2);
    const float b0 = bias[nb + 0], b1 = bias[nb + 1];
    const float b2 = bias[nb + 2], b3 = bias[nb + 3];
    #pragma unroll
    for (int i = 0; i < 4; ++i) {
        int m = m0 + (ty << 2) + i;
        int b = m >> 10, l = m & 1023;
        float4 o;
        o.x = (acc[i][0] + b0) * scale;
        o.y = (acc[i][1] + b1) * scale;
        o.z = (acc[i][2] + b2) * scale;
        o.w = (acc[i][3] + b3) * scale;
        *(float4*)&dst[(((b * 16 + h) * 1024 + l) << 6) + (tx << 2)] = o;
    }
}

// ---------------------------------------------------------------------------
// Stage 2: bias_r[row, r] = g_Q[row,:] . rel_pe[r,:], row in [0, 65536)
// One CTA = 32 rows; rel_pe (33 KB) + 32 q rows (8 KB) in smem.
// ---------------------------------------------------------------------------
__global__ __launch_bounds__(256) void bias_gemm(const float* __restrict__ pe)
{
    __shared__ float pes[129 * 64];
    __shared__ float qs[32 * 64];
    const int tid = threadIdx.x;
    const int row0 = blockIdx.x << 5;
    for (int i = tid; i < 129 * 64; i += 256) pes[i] = pe[i];
    for (int i = tid; i < 32 * 64; i += 256) qs[i] = g_Q[row0 * 64 + i];
    __syncthreads();
    for (int idx = tid; idx < 32 * 129; idx += 256) {
        int r = idx / 129, c = idx - r * 129;
        float s = 0.f;
        #pragma unroll
        for (int d = 0; d < 64; d += 4) {
            float4 a = *(const float4*)&qs[(r << 6) + d];
            float4 p = *(const float4*)&pes[(c << 6) + d];
            s = fmaf(a.x, p.x, s); s = fmaf(a.y, p.y, s);
            s = fmaf(a.z, p.z, s); s = fmaf(a.w, p.w, s);
        }
        g_bias[(row0 + r) * BSTR + c] = s;
    }
}

// ---------------------------------------------------------------------------
// Stage 3: flash attention. grid (16 i-tiles, 64 bh). 64x64 tiles, D=64.
// Dynamic smem: Qt/Kt/Vs/Pt (16KB each) + bias tile 64x130 (33.3KB) = 96.5KB
// ---------------------------------------------------------------------------
#define ATTN_SMEM ((4096 * 4 + 64 * 130) * 4)

__global__ __launch_bounds__(256) void attn_kernel()
{
    extern __shared__ float sm[];
    float* Qt = sm;              // [d][m]
    float* Kt = sm + 4096;       // [d][n]
    float* Vs = sm + 8192;       // [j][d]
    float* Pt = sm + 12288;      // [j][m]
    float* Bm = sm + 16384;      // [64][130], col 64 == delta 0

    const int bh = blockIdx.y;
    const int i0 = blockIdx.x << 6;
    const int tid = threadIdx.x;
    const int tx = tid & 15, ty = tid >> 4;
    const int lr = tid >> 2;
    const int lc = (tid & 3) << 2;

    const float* Qg = g_Q + (bh * 1024 + i0) * 64;
    const float* Kg = g_K + bh * 1024 * 64;
    const float* Vg = g_V + bh * 1024 * 64;

    // load full Q tile transposed: 64 rows x 64 d -> 16 floats per thread
    #pragma unroll
    for (int c = 0; c < 4; ++c) {
        int d0 = (c << 4) + lc;
        float4 a = *(const float4*)&Qg[lr * 64 + d0];
        Qt[(d0 + 0) * 64 + lr] = a.x; Qt[(d0 + 1) * 64 + lr] = a.y;
        Qt[(d0 + 2) * 64 + lr] = a.z; Qt[(d0 + 3) * 64 + lr] = a.w;
    }
    for (int idx = tid; idx < 64 * 129; idx += 256) {
        int r = idx / 129, c = idx - r * 129;
        Bm[r * 130 + c] = g_bias[(bh * 1024 + i0 + r) * BSTR + c];
    }

    float m_r[4] = {-1e30f, -1e30f, -1e30f, -1e30f};
    float l_r[4] = {0.f, 0.f, 0.f, 0.f};
    float Oa[4][4] = {};

    for (int j0 = 0; j0 < 1024; j0 += 64) {
        __syncthreads();
        // load full K tile (transposed) and V tile: 16 floats per thread each
        #pragma unroll
        for (int c = 0; c < 4; ++c) {
            int d0 = (c << 4) + lc;
            float4 kv = *(const float4*)&Kg[(j0 + lr) * 64 + d0];
            Kt[(d0 + 0) * 64 + lr] = kv.x; Kt[(d0 + 1) * 64 + lr] = kv.y;
            Kt[(d0 + 2) * 64 + lr] = kv.z; Kt[(d0 + 3) * 64 + lr] = kv.w;
            float4 vv = *(const float4*)&Vg[(j0 + lr) * 64 + d0];
            *(float4*)&Vs[lr * 64 + d0] = vv;
        }
        __syncthreads();

        // S = Q K^T
        float S[4][4] = {};
        #pragma unroll
        for (int k = 0; k < 64; ++k) {
            float4 av = *(const float4*)&Qt[(k << 6) + (ty << 2)];
            float4 bv = *(const float4*)&Kt[(k << 6) + (tx << 2)];
            float am[4] = {av.x, av.y, av.z, av.w};
            float bm[4] = {bv.x, bv.y, bv.z, bv.w};
            #pragma unroll
            for (int i = 0; i < 4; ++i)
                #pragma unroll
                for (int j = 0; j < 4; ++j)
                    S[i][j] = fmaf(am[i], bm[j], S[i][j]);
        }

        // relative-PE bias gather: delta = j_glob - i_glob clipped to [-64,64]
        const int base_dj = j0 - i0 + (tx << 2) - (ty << 2);
        #pragma unroll
        for (int i = 0; i < 4; ++i) {
            const float* brow = &Bm[((ty << 2) + i) * 130 + 64];
            #pragma unroll
            for (int j = 0; j < 4; ++j) {
                int dd = base_dj + j - i;
                dd = dd < -64 ? -64 : (dd > 64 ? 64 : dd);
                S[i][j] += brow[dd];
            }
        }

        // online softmax (row groups = 16 lanes sharing ty)
        #pragma unroll
        for (int i = 0; i < 4; ++i) {
            float mx = fmaxf(fmaxf(S[i][0], S[i][1]), fmaxf(S[i][2], S[i][3]));
            #pragma unroll
            for (int o = 8; o >= 1; o >>= 1)
                mx = fmaxf(mx, __shfl_xor_sync(0xffffffffu, mx, o));
            float newm = fmaxf(m_r[i], mx);
            float sc = __expf(m_r[i] - newm);
            float ps = 0.f;
            #pragma unroll
            for (int j = 0; j < 4; ++j) {
                S[i][j] = __expf(S[i][j] - newm);
                ps += S[i][j];
            }
            #pragma unroll
            for (int o = 8; o >= 1; o >>= 1)
                ps += __shfl_xor_sync(0xffffffffu, ps, o);
            l_r[i] = l_r[i] * sc + ps;
            m_r[i] = newm;
            #pragma unroll
            for (int j = 0; j < 4; ++j) Oa[i][j] *= sc;
        }

        // stage P (transposed) then O += P @ V
        #pragma unroll
        for (int j = 0; j < 4; ++j)
            #pragma unroll
            for (int i = 0; i < 4; ++i)
                Pt[((tx << 2) + j) * 64 + (ty << 2) + i] = S[i][j];
        __syncthreads();
        #pragma unroll
        for (int jj = 0; jj < 64; ++jj) {
            float4 pv = *(const float4*)&Pt[(jj << 6) + (ty << 2)];
            float4 vv2 = *(const float4*)&Vs[(jj << 6) + (tx << 2)];
            float pm[4] = {pv.x, pv.y, pv.z, pv.w};
            float vm[4] = {vv2.x, vv2.y, vv2.z, vv2.w};
            #pragma unroll
            for (int i = 0; i < 4; ++i)
                #pragma unroll
                for (int j = 0; j < 4; ++j)
                    Oa[i][j] = fmaf(pm[i], vm[j], Oa[i][j]);
        }
    }

    #pragma unroll
    for (int i = 0; i < 4; ++i) {
        float inv = 1.0f / l_r[i];
        float4 o;
        o.x = Oa[i][0] * inv; o.y = Oa[i][1] * inv;
        o.z = Oa[i][2] * inv; o.w = Oa[i][3] * inv;
        *(float4*)&g_O[(bh * 1024 + i0 + (ty << 2) + i) * 64 + (tx << 2)] = o;
    }
}

// ---------------------------------------------------------------------------
// Stage 4: out = X @ out_w^T + out_b, X[m,k] gathered from g_O (b,h,l,d)
// M=4096, N=1024, K=1024
// ---------------------------------------------------------------------------
__global__ __launch_bounds__(256) void out_gemm(
    const float* __restrict__ W,     // [1024,1024]
    const float* __restrict__ bias,  // [1024]
    float* __restrict__ out)         // [4096,1024]
{
    __shared__ float As[16][64];
    __shared__ float Bs[16][64];
    const int m0 = blockIdx.y << 6;
    const int n0 = blockIdx.x << 6;
    const int tid = threadIdx.x;
    const int tx = tid & 15, ty = tid >> 4;
    const int lr = tid >> 2;
    const int lc = (tid & 3) << 2;

    float acc[4][4] = {};
    const int m = m0 + lr;
    const int b = m >> 10, l = m & 1023;
    const float* Wp = W + (n0 + lr) * 1024 + lc;

    for (int k0 = 0; k0 < 1024; k0 += 16) {
        const int k = k0 + lc;  // 4 consecutive k stay within one head (4-aligned)
        float4 a = *(const float4*)&g_O[(((b * 16 + (k >> 6)) * 1024 + l) << 6) + (k & 63)];
        float4 w = *(const float4*)(Wp + k0);
        __syncthreads();
        As[lc + 0][lr] = a.x; As[lc + 1][lr] = a.y;
        As[lc + 2][lr] = a.z; As[lc + 3][lr] = a.w;
        Bs[lc + 0][lr] = w.x; Bs[lc + 1][lr] = w.y;
        Bs[lc + 2][lr] = w.z; Bs[lc + 3][lr] = w.w;
        __syncthreads();
        #pragma unroll
        for (int k2 = 0; k2 < 16; ++k2) {
            float4 av = *(const float4*)&As[k2][ty << 2];
            float4 bv = *(const float4*)&Bs[k2][tx << 2];
            float am[4] = {av.x, av.y, av.z, av.w};
            float bm[4] = {bv.x, bv.y, bv.z, bv.w};
            #pragma unroll
            for (int i = 0; i < 4; ++i)
                #pragma unroll
                for (int j = 0; j < 4; ++j)
                    acc[i][j] = fmaf(am[i], bm[j], acc[i][j]);
        }
    }

    const int nb = n0 + (tx << 2);
    const float b0 = bias[nb + 0], b1 = bias[nb + 1];
    const float b2 = bias[nb + 2], b3 = bias[nb + 3];
    #pragma unroll
    for (int i = 0; i < 4; ++i) {
        int mm = m0 + (ty << 2) + i;
        float4 o;
        o.x = acc[i][0] + b0; o.y = acc[i][1] + b1;
        o.z = acc[i][2] + b2; o.w = acc[i][3] + b3;
        *(float4*)&out[mm * 1024 + nb] = o;
    }
}

// ---------------------------------------------------------------------------
extern "C" void kernel_launch(void* const* d_in, const int* in_sizes, int n_in,
                              void* d_out, int out_size)
{
    const float* q  = (const float*)d_in[0];
    const float* w3 = (const float*)d_in[1];
    const float* b3 = (const float*)d_in[2];
    const float* ow = (const float*)d_in[3];
    const float* ob = (const float*)d_in[4];
    const float* pe = (const float*)d_in[5];
    float* out = (float*)d_out;

    cudaFuncSetAttribute(attn_kernel, cudaFuncAttributeMaxDynamicSharedMemorySize,
                         ATTN_SMEM);

    qkv_gemm<<<dim3(48, 64), 256>>>(q, w3, b3);
    bias_gemm<<<2048, 256>>>(pe);
    attn_kernel<<<dim3(16, 64), 256, ATTN_SMEM>>>();
    out_gemm<<<dim3(16, 64), 256>>>(ow, ob, out);
}

// round 4
// speedup vs baseline: 1.4299x; 1.4299x over previous
#include <cuda_runtime.h>
#include <cuda_bf16.h>
#include <cstdint>

// ---------------------------------------------------------------------------
// RelativeSelfAttention: B=4, L=1024, E=1024, H=16, D=64, K=64 (129 PE rows)
// R4: stages 1 & 4 via mma.sync bf16 (3-term split, fp32 accum) — baseline PTX
// (tcgen05 unavailable: harness compiles via compute_103, no 'a' features)
// ---------------------------------------------------------------------------

#define NBH   64
#define BSTR  132

__device__ float g_Q[NBH * 1024 * 64];
__device__ float g_K[NBH * 1024 * 64];
__device__ float g_V[NBH * 1024 * 64];
__device__ float g_O[NBH * 1024 * 64];
__device__ float g_bias[NBH * 1024 * BSTR];

__device__ __nv_bfloat16 g_Ahi[4096 * 1024], g_Alo[4096 * 1024];
__device__ __nv_bfloat16 g_Whi[3072 * 1024], g_Wlo[3072 * 1024];
__device__ __nv_bfloat16 g_OWhi[1024 * 1024], g_OWlo[1024 * 1024];
__device__ __nv_bfloat16 g_Xhi[4096 * 1024], g_Xlo[4096 * 1024];

// ------------------------------- PTX helpers -------------------------------
__device__ __forceinline__ uint32_t s2u(const void* p) {
    return (uint32_t)__cvta_generic_to_shared(p);
}
__device__ __forceinline__ void ldsm_x4(uint32_t* r, uint32_t addr) {
    asm volatile("ldmatrix.sync.aligned.m8n8.x4.shared.b16 {%0,%1,%2,%3}, [%4];"
        : "=r"(r[0]), "=r"(r[1]), "=r"(r[2]), "=r"(r[3]) : "r"(addr));
}
__device__ __forceinline__ void ldsm_x2(uint32_t* r, uint32_t addr) {
    asm volatile("ldmatrix.sync.aligned.m8n8.x2.shared.b16 {%0,%1}, [%2];"
        : "=r"(r[0]), "=r"(r[1]) : "r"(addr));
}
__device__ __forceinline__ void mma16816(float* c, const uint32_t* a,
                                         const uint32_t* b) {
    asm volatile(
        "mma.sync.aligned.m16n8k16.row.col.f32.bf16.bf16.f32 "
        "{%0,%1,%2,%3}, {%4,%5,%6,%7}, {%8,%9}, {%0,%1,%2,%3};"
        : "+f"(c[0]), "+f"(c[1]), "+f"(c[2]), "+f"(c[3])
        : "r"(a[0]), "r"(a[1]), "r"(a[2]), "r"(a[3]), "r"(b[0]), "r"(b[1]));
}

// ---------------------------------------------------------------------------
// fp32 -> bf16 hi/lo split (which: 0=A(q), 1=W3, 2=out_w)
// ---------------------------------------------------------------------------
__global__ __launch_bounds__(256) void split_kernel(
    const float* __restrict__ src, int n4, int which)
{
    int i = blockIdx.x * 256 + threadIdx.x;
    if (i >= n4) return;
    float4 v = ((const float4*)src)[i];
    __nv_bfloat16 h[4], l[4];
    float f[4] = {v.x, v.y, v.z, v.w};
    #pragma unroll
    for (int k = 0; k < 4; ++k) {
        h[k] = __float2bfloat16(f[k]);
        l[k] = __float2bfloat16(f[k] - __bfloat162float(h[k]));
    }
    __nv_bfloat16* hp = which == 0 ? g_Ahi : (which == 1 ? g_Whi : g_OWhi);
    __nv_bfloat16* lp = which == 0 ? g_Alo : (which == 1 ? g_Wlo : g_OWlo);
    *(uint2*)&hp[i * 4] = *(uint2*)h;
    *(uint2*)&lp[i * 4] = *(uint2*)l;
}

// g_O (bh,l,d) -> X (b,l,e) bf16 hi/lo
__global__ __launch_bounds__(256) void gather_split(void)
{
    int i = blockIdx.x * 256 + threadIdx.x;
    int m = i >> 8;
    int c4 = i & 255;
    int e = c4 << 2;
    int h = e >> 6, d = e & 63;
    int b = m >> 10, l = m & 1023;
    float4 v = *(const float4*)&g_O[(((b << 4) + h) * 1024 + l) * 64 + d];
    __nv_bfloat16 hh[4], ll[4];
    float f[4] = {v.x, v.y, v.z, v.w};
    #pragma unroll
    for (int k = 0; k < 4; ++k) {
        hh[k] = __float2bfloat16(f[k]);
        ll[k] = __float2bfloat16(f[k] - __bfloat162float(hh[k]));
    }
    *(uint2*)&g_Xhi[m * 1024 + e] = *(uint2*)hh;
    *(uint2*)&g_Xlo[m * 1024 + e] = *(uint2*)ll;
}

// ---------------------------------------------------------------------------
// Split-bf16 mma.sync GEMM: D[m,n] = sum_k A[m,k]*B[n,k]  (+bias epilogue)
// MODE 0: A=q-split,B=W3-split -> scatter g_Q(x0.125)/g_K/g_V
// MODE 1: A=X-split,B=out_w-split -> outp
// CTA tile 128x128, 8 warps (2m x 4n), warp tile 64x32, K-chunk 32.
// smem rows padded to 40 bf16 (80B) -> conflict-free ldmatrix.
// ---------------------------------------------------------------------------
#define SPAD 40

template <int MODE>
__global__ __launch_bounds__(256) void mma_gemm(
    const float* __restrict__ bias, float* __restrict__ outp)
{
    __shared__ __nv_bfloat16 sAh[128 * SPAD], sAl[128 * SPAD];
    __shared__ __nv_bfloat16 sBh[128 * SPAD], sBl[128 * SPAD];

    const __nv_bfloat16* Ah = (MODE == 0) ? g_Ahi : g_Xhi;
    const __nv_bfloat16* Al = (MODE == 0) ? g_Alo : g_Xlo;
    const __nv_bfloat16* Bh = (MODE == 0) ? g_Whi : g_OWhi;
    const __nv_bfloat16* Bl = (MODE == 0) ? g_Wlo : g_OWlo;

    const int m0 = blockIdx.y << 7;
    const int n0 = blockIdx.x << 7;
    const int tid = threadIdx.x;
    const int wid = tid >> 5, lane = tid & 31;
    const int wm = wid >> 2, wn = wid & 3;
    const int grp = lane >> 2, tig = lane & 3;

    // loader: 2 uint4 per thread per array per chunk
    const int id0 = tid, id1 = tid + 256;
    const int lrow0 = id0 >> 2, lc40 = id0 & 3;
    const int lrow1 = id1 >> 2, lc41 = id1 & 3;
    const int so0 = lrow0 * SPAD + lc40 * 8;   // bf16 units
    const int so1 = lrow1 * SPAD + lc41 * 8;

    // ldmatrix per-lane smem byte offsets
    const uint32_t aBase = (uint32_t)(((wm * 64) + (lane & 15)) * SPAD +
                                      (lane >> 4) * 8) * 2;
    const uint32_t bBase = (uint32_t)(((wn * 32) + (lane & 7)) * SPAD +
                                      ((lane >> 3) & 1) * 8) * 2;
    const uint32_t uAh = s2u(sAh), uAl = s2u(sAl);
    const uint32_t uBh = s2u(sBh), uBl = s2u(sBl);

    float acc[4][4][4] = {};

    uint4 rAh0, rAh1, rAl0, rAl1, rBh0, rBh1, rBl0, rBl1;
    // prologue: load chunk 0
    {
        size_t ga0 = (size_t)(m0 + lrow0) * 128 + lc40;
        size_t ga1 = (size_t)(m0 + lrow1) * 128 + lc41;
        size_t gb0 = (size_t)(n0 + lrow0) * 128 + lc40;
        size_t gb1 = (size_t)(n0 + lrow1) * 128 + lc41;
        rAh0 = ((const uint4*)Ah)[ga0]; rAh1 = ((const uint4*)Ah)[ga1];
        rAl0 = ((const uint4*)Al)[ga0]; rAl1 = ((const uint4*)Al)[ga1];
        rBh0 = ((const uint4*)Bh)[gb0]; rBh1 = ((const uint4*)Bh)[gb1];
        rBl0 = ((const uint4*)Bl)[gb0]; rBl1 = ((const uint4*)Bl)[gb1];
    }

    for (int kc = 0; kc < 32; ++kc) {
        *(uint4*)&sAh[so0] = rAh0; *(uint4*)&sAh[so1] = rAh1;
        *(uint4*)&sAl[so0] = rAl0; *(uint4*)&sAl[so1] = rAl1;
        *(uint4*)&sBh[so0] = rBh0; *(uint4*)&sBh[so1] = rBh1;
        *(uint4*)&sBl[so0] = rBl0; *(uint4*)&sBl[so1] = rBl1;
        __syncthreads();

        if (kc + 1 < 32) {   // prefetch next chunk
            int ko = (kc + 1) * 4;
            size_t ga0 = (size_t)(m0 + lrow0) * 128 + ko + lc40;
            size_t ga1 = (size_t)(m0 + lrow1) * 128 + ko + lc41;
            size_t gb0 = (size_t)(n0 + lrow0) * 128 + ko + lc40;
            size_t gb1 = (size_t)(n0 + lrow1) * 128 + ko + lc41;
            rAh0 = ((const uint4*)Ah)[ga0]; rAh1 = ((const uint4*)Ah)[ga1];
            rAl0 = ((const uint4*)Al)[ga0]; rAl1 = ((const uint4*)Al)[ga1];
            rBh0 = ((const uint4*)Bh)[gb0]; rBh1 = ((const uint4*)Bh)[gb1];
            rBl0 = ((const uint4*)Bl)[gb0]; rBl1 = ((const uint4*)Bl)[gb1];
        }

        #pragma unroll
        for (int ks = 0; ks < 2; ++ks) {
            const uint32_t kb = (uint32_t)(ks * 16) * 2;
            uint32_t fah[4][4], fal[4][4], fbh[4][2], fbl[4][2];
            #pragma unroll
            for (int mi = 0; mi < 4; ++mi) {
                uint32_t off = aBase + kb + (uint32_t)(mi * 16 * SPAD) * 2;
                ldsm_x4(fah[mi], uAh + off);
                ldsm_x4(fal[mi], uAl + off);
            }
            #pragma unroll
            for (int ni = 0; ni < 4; ++ni) {
                uint32_t off = bBase + kb + (uint32_t)(ni * 8 * SPAD) * 2;
                ldsm_x2(fbh[ni], uBh + off);
                ldsm_x2(fbl[ni], uBl + off);
            }
            #pragma unroll
            for (int mi = 0; mi < 4; ++mi)
                #pragma unroll
                for (int ni = 0; ni < 4; ++ni) {
                    mma16816(acc[mi][ni], fah[mi], fbh[ni]);
                    mma16816(acc[mi][ni], fah[mi], fbl[ni]);
                    mma16816(acc[mi][ni], fal[mi], fbh[ni]);
                }
        }
        __syncthreads();
    }

    // epilogue straight from registers
    #pragma unroll
    for (int mi = 0; mi < 4; ++mi) {
        #pragma unroll
        for (int ni = 0; ni < 4; ++ni) {
            const int col = n0 + wn * 32 + ni * 8 + tig * 2;
            const float bv0 = bias[col], bv1 = bias[col + 1];
            #pragma unroll
            for (int rh = 0; rh < 2; ++rh) {
                const int row = m0 + wm * 64 + mi * 16 + grp + rh * 8;
                float v0 = acc[mi][ni][rh * 2 + 0] + bv0;
                float v1 = acc[mi][ni][rh * 2 + 1] + bv1;
                if (MODE == 0) {
                    const int part = col >> 10;
                    const int h = (col & 1023) >> 6;
                    const int d = col & 63;
                    float* dst = part == 0 ? g_Q : (part == 1 ? g_K : g_V);
                    const float sc = part == 0 ? 0.125f : 1.0f;
                    const int b = row >> 10, l = row & 1023;
                    float2 o = {v0 * sc, v1 * sc};
                    *(float2*)&dst[(((b << 4) + h) * 1024 + l) * 64 + d] = o;
                } else {
                    float2 o = {v0, v1};
                    *(float2*)&outp[row * 1024 + col] = o;
                }
            }
        }
    }
}

// ---------------------------------------------------------------------------
// Stage 2: bias_r[row, r] = g_Q[row,:] . rel_pe[r,:]  (unchanged)
// ---------------------------------------------------------------------------
__global__ __launch_bounds__(256) void bias_gemm(const float* __restrict__ pe)
{
    __shared__ float pes[129 * 64];
    __shared__ float qs[32 * 64];
    const int tid = threadIdx.x;
    const int row0 = blockIdx.x << 5;
    for (int i = tid; i < 129 * 64; i += 256) pes[i] = pe[i];
    for (int i = tid; i < 32 * 64; i += 256) qs[i] = g_Q[row0 * 64 + i];
    __syncthreads();
    for (int idx = tid; idx < 32 * 129; idx += 256) {
        int r = idx / 129, c = idx - r * 129;
        float s = 0.f;
        #pragma unroll
        for (int d = 0; d < 64; d += 4) {
            float4 a = *(const float4*)&qs[(r << 6) + d];
            float4 p = *(const float4*)&pes[(c << 6) + d];
            s = fmaf(a.x, p.x, s); s = fmaf(a.y, p.y, s);
            s = fmaf(a.z, p.z, s); s = fmaf(a.w, p.w, s);
        }
        g_bias[(row0 + r) * BSTR + c] = s;
    }
}

// ---------------------------------------------------------------------------
// Stage 3: flash attention (unchanged from R2)
// ---------------------------------------------------------------------------
#define ATTN_SMEM ((4096 * 4 + 64 * 130) * 4)

__global__ __launch_bounds__(256) void attn_kernel()
{
    extern __shared__ float sm[];
    float* Qt = sm;
    float* Kt = sm + 4096;
    float* Vs = sm + 8192;
    float* Pt = sm + 12288;
    float* Bm = sm + 16384;

    const int bh = blockIdx.y;
    const int i0 = blockIdx.x << 6;
    const int tid = threadIdx.x;
    const int tx = tid & 15, ty = tid >> 4;
    const int lr = tid >> 2;
    const int lc = (tid & 3) << 2;

    const float* Qg = g_Q + (bh * 1024 + i0) * 64;
    const float* Kg = g_K + bh * 1024 * 64;
    const float* Vg = g_V + bh * 1024 * 64;

    #pragma unroll
    for (int c = 0; c < 4; ++c) {
        int d0 = (c << 4) + lc;
        float4 a = *(const float4*)&Qg[lr * 64 + d0];
        Qt[(d0 + 0) * 64 + lr] = a.x; Qt[(d0 + 1) * 64 + lr] = a.y;
        Qt[(d0 + 2) * 64 + lr] = a.z; Qt[(d0 + 3) * 64 + lr] = a.w;
    }
    for (int idx = tid; idx < 64 * 129; idx += 256) {
        int r = idx / 129, c = idx - r * 129;
        Bm[r * 130 + c] = g_bias[(bh * 1024 + i0 + r) * BSTR + c];
    }

    float m_r[4] = {-1e30f, -1e30f, -1e30f, -1e30f};
    float l_r[4] = {0.f, 0.f, 0.f, 0.f};
    float Oa[4][4] = {};

    for (int j0 = 0; j0 < 1024; j0 += 64) {
        __syncthreads();
        #pragma unroll
        for (int c = 0; c < 4; ++c) {
            int d0 = (c << 4) + lc;
            float4 kv = *(const float4*)&Kg[(j0 + lr) * 64 + d0];
            Kt[(d0 + 0) * 64 + lr] = kv.x; Kt[(d0 + 1) * 64 + lr] = kv.y;
            Kt[(d0 + 2) * 64 + lr] = kv.z; Kt[(d0 + 3) * 64 + lr] = kv.w;
            float4 vv = *(const float4*)&Vg[(j0 + lr) * 64 + d0];
            *(float4*)&Vs[lr * 64 + d0] = vv;
        }
        __syncthreads();

        float S[4][4] = {};
        #pragma unroll
        for (int k = 0; k < 64; ++k) {
            float4 av = *(const float4*)&Qt[(k << 6) + (ty << 2)];
            float4 bv = *(const float4*)&Kt[(k << 6) + (tx << 2)];
            float am[4] = {av.x, av.y, av.z, av.w};
            float bm[4] = {bv.x, bv.y, bv.z, bv.w};
            #pragma unroll
            for (int i = 0; i < 4; ++i)
                #pragma unroll
                for (int j = 0; j < 4; ++j)
                    S[i][j] = fmaf(am[i], bm[j], S[i][j]);
        }

        const int base_dj = j0 - i0 + (tx << 2) - (ty << 2);
        #pragma unroll
        for (int i = 0; i < 4; ++i) {
            const float* brow = &Bm[((ty << 2) + i) * 130 + 64];
            #pragma unroll
            for (int j = 0; j < 4; ++j) {
                int dd = base_dj + j - i;
                dd = dd < -64 ? -64 : (dd > 64 ? 64 : dd);
                S[i][j] += brow[dd];
            }
        }

        #pragma unroll
        for (int i = 0; i < 4; ++i) {
            float mx = fmaxf(fmaxf(S[i][0], S[i][1]), fmaxf(S[i][2], S[i][3]));
            #pragma unroll
            for (int o = 8; o >= 1; o >>= 1)
                mx = fmaxf(mx, __shfl_xor_sync(0xffffffffu, mx, o));
            float newm = fmaxf(m_r[i], mx);
            float sc = __expf(m_r[i] - newm);
            float ps = 0.f;
            #pragma unroll
            for (int j = 0; j < 4; ++j) {
                S[i][j] = __expf(S[i][j] - newm);
                ps += S[i][j];
            }
            #pragma unroll
            for (int o = 8; o >= 1; o >>= 1)
                ps += __shfl_xor_sync(0xffffffffu, ps, o);
            l_r[i] = l_r[i] * sc + ps;
            m_r[i] = newm;
            #pragma unroll
            for (int j = 0; j < 4; ++j) Oa[i][j] *= sc;
        }

        #pragma unroll
        for (int j = 0; j < 4; ++j)
            #pragma unroll
            for (int i = 0; i < 4; ++i)
                Pt[((tx << 2) + j) * 64 + (ty << 2) + i] = S[i][j];
        __syncthreads();
        #pragma unroll
        for (int jj = 0; jj < 64; ++jj) {
            float4 pv = *(const float4*)&Pt[(jj << 6) + (ty << 2)];
            float4 vv2 = *(const float4*)&Vs[(jj << 6) + (tx << 2)];
            float pm[4] = {pv.x, pv.y, pv.z, pv.w};
            float vm[4] = {vv2.x, vv2.y, vv2.z, vv2.w};
            #pragma unroll
            for (int i = 0; i < 4; ++i)
                #pragma unroll
                for (int j = 0; j < 4; ++j)
                    Oa[i][j] = fmaf(pm[i], vm[j], Oa[i][j]);
        }
    }

    #pragma unroll
    for (int i = 0; i < 4; ++i) {
        float inv = 1.0f / l_r[i];
        float4 o;
        o.x = Oa[i][0] * inv; o.y = Oa[i][1] * inv;
        o.z = Oa[i][2] * inv; o.w = Oa[i][3] * inv;
        *(float4*)&g_O[(bh * 1024 + i0 + (ty << 2) + i) * 64 + (tx << 2)] = o;
    }
}

// ---------------------------------------------------------------------------
extern "C" void kernel_launch(void* const* d_in, const int* in_sizes, int n_in,
                              void* d_out, int out_size)
{
    const float* q  = (const float*)d_in[0];
    const float* w3 = (const float*)d_in[1];
    const float* b3 = (const float*)d_in[2];
    const float* ow = (const float*)d_in[3];
    const float* ob = (const float*)d_in[4];
    const float* pe = (const float*)d_in[5];
    float* out = (float*)d_out;

    cudaFuncSetAttribute(attn_kernel, cudaFuncAttributeMaxDynamicSharedMemorySize,
                         ATTN_SMEM);

    split_kernel<<<4096, 256>>>(q,  4096 * 1024 / 4, 0);
    split_kernel<<<3072, 256>>>(w3, 3072 * 1024 / 4, 1);
    split_kernel<<<1024, 256>>>(ow, 1024 * 1024 / 4, 2);

    mma_gemm<0><<<dim3(24, 32), 256>>>(b3, nullptr);
    bias_gemm<<<2048, 256>>>(pe);
    attn_kernel<<<dim3(16, 64), 256, ATTN_SMEM>>>();
    gather_split<<<4096, 256>>>();
    mma_gemm<1><<<dim3(8, 32), 256>>>(ob, out);
}

// round 5
// speedup vs baseline: 1.8437x; 1.2893x over previous
#include <cuda_runtime.h>
#include <cuda_bf16.h>
#include <cstdint>

// ---------------------------------------------------------------------------
// RelativeSelfAttention: B=4, L=1024, E=1024, H=16, D=64, K=64 (129 PE rows)
// R5: all GEMMs + attention on mma.sync bf16 (3-term split, fp32 accum)
// ---------------------------------------------------------------------------

#define NBH   64
#define BSTR  132

__device__ float g_Q[NBH * 1024 * 64];          // scaled fp32 Q (for bias_gemm)
__device__ float g_bias[NBH * 1024 * BSTR];

__device__ __nv_bfloat16 g_Ahi[4096 * 1024], g_Alo[4096 * 1024];
__device__ __nv_bfloat16 g_Whi[3072 * 1024], g_Wlo[3072 * 1024];
__device__ __nv_bfloat16 g_OWhi[1024 * 1024], g_OWlo[1024 * 1024];
__device__ __nv_bfloat16 g_Xhi[4096 * 1024], g_Xlo[4096 * 1024];
__device__ __nv_bfloat16 g_Qhi[NBH * 65536], g_Qlo[NBH * 65536];
__device__ __nv_bfloat16 g_Khi[NBH * 65536], g_Klo[NBH * 65536];
__device__ __nv_bfloat16 g_Vhi[NBH * 65536], g_Vlo[NBH * 65536];

// ------------------------------- PTX helpers -------------------------------
__device__ __forceinline__ uint32_t s2u(const void* p) {
    return (uint32_t)__cvta_generic_to_shared(p);
}
__device__ __forceinline__ void ldsm_x4(uint32_t* r, uint32_t addr) {
    asm volatile("ldmatrix.sync.aligned.m8n8.x4.shared.b16 {%0,%1,%2,%3}, [%4];"
        : "=r"(r[0]), "=r"(r[1]), "=r"(r[2]), "=r"(r[3]) : "r"(addr));
}
__device__ __forceinline__ void ldsm_x4_t(uint32_t* r, uint32_t addr) {
    asm volatile("ldmatrix.sync.aligned.m8n8.x4.trans.shared.b16 {%0,%1,%2,%3}, [%4];"
        : "=r"(r[0]), "=r"(r[1]), "=r"(r[2]), "=r"(r[3]) : "r"(addr));
}
__device__ __forceinline__ void mma16816(float* c, const uint32_t* a,
                                         const uint32_t* b) {
    asm volatile(
        "mma.sync.aligned.m16n8k16.row.col.f32.bf16.bf16.f32 "
        "{%0,%1,%2,%3}, {%4,%5,%6,%7}, {%8,%9}, {%0,%1,%2,%3};"
        : "+f"(c[0]), "+f"(c[1]), "+f"(c[2]), "+f"(c[3])
        : "r"(a[0]), "r"(a[1]), "r"(a[2]), "r"(a[3]), "r"(b[0]), "r"(b[1]));
}
// pack (v0,v1) into bf16x2 hi + bf16x2 lo-residual (v0 in low half)
__device__ __forceinline__ void pack_hl(float v0, float v1,
                                        uint32_t& hi, uint32_t& lo) {
    __nv_bfloat16 h0 = __float2bfloat16(v0), h1 = __float2bfloat16(v1);
    float l0 = v0 - __bfloat162float(h0), l1 = v1 - __bfloat162float(h1);
    __nv_bfloat162 H; H.x = h0; H.y = h1;
    __nv_bfloat162 L; L.x = __float2bfloat16(l0); L.y = __float2bfloat16(l1);
    hi = *(uint32_t*)&H; lo = *(uint32_t*)&L;
}
__device__ __forceinline__ void split2(__nv_bfloat16* hp, __nv_bfloat16* lp,
                                       size_t idx, float v0, float v1) {
    uint32_t hi, lo;
    pack_hl(v0, v1, hi, lo);
    *(uint32_t*)&hp[idx] = hi;
    *(uint32_t*)&lp[idx] = lo;
}

// ---------------------------------------------------------------------------
// fp32 -> bf16 hi/lo split (which: 0=A(q), 1=W3, 2=out_w)
// ---------------------------------------------------------------------------
__global__ __launch_bounds__(256) void split_kernel(
    const float* __restrict__ src, int n4, int which)
{
    int i = blockIdx.x * 256 + threadIdx.x;
    if (i >= n4) return;
    float4 v = ((const float4*)src)[i];
    __nv_bfloat16 h[4], l[4];
    float f[4] = {v.x, v.y, v.z, v.w};
    #pragma unroll
    for (int k = 0; k < 4; ++k) {
        h[k] = __float2bfloat16(f[k]);
        l[k] = __float2bfloat16(f[k] - __bfloat162float(h[k]));
    }
    __nv_bfloat16* hp = which == 0 ? g_Ahi : (which == 1 ? g_Whi : g_OWhi);
    __nv_bfloat16* lp = which == 0 ? g_Alo : (which == 1 ? g_Wlo : g_OWlo);
    *(uint2*)&hp[i * 4] = *(uint2*)h;
    *(uint2*)&lp[i * 4] = *(uint2*)l;
}

// ---------------------------------------------------------------------------
// Split-bf16 mma.sync GEMM (double-buffered smem).
// MODE 0: A=q-split,B=W3-split -> g_Q fp32 (x0.125) + Q/K/V bf16-split
// MODE 1: A=X-split,B=out_w-split -> outp
// CTA tile 128x128, 8 warps (2m x 4n), warp tile 64x32, K-chunk 32.
// ---------------------------------------------------------------------------
#define SPAD 40
#define ARR_BYTES (128 * SPAD * 2)
#define GEMM_SMEM (2 * 4 * ARR_BYTES)

template <int MODE>
__global__ __launch_bounds__(256) void mma_gemm(
    const float* __restrict__ bias, float* __restrict__ outp)
{
    extern __shared__ __align__(16) char gsm[];
    __nv_bfloat16* bufs = (__nv_bfloat16*)gsm;
    const uint32_t u0 = s2u(gsm);

    const __nv_bfloat16* Ah = (MODE == 0) ? g_Ahi : g_Xhi;
    const __nv_bfloat16* Al = (MODE == 0) ? g_Alo : g_Xlo;
    const __nv_bfloat16* Bh = (MODE == 0) ? g_Whi : g_OWhi;
    const __nv_bfloat16* Bl = (MODE == 0) ? g_Wlo : g_OWlo;

    const int m0 = blockIdx.y << 7;
    const int n0 = blockIdx.x << 7;
    const int tid = threadIdx.x;
    const int wid = tid >> 5, lane = tid & 31;
    const int wm = wid >> 2, wn = wid & 3;
    const int grp = lane >> 2, tig = lane & 3;

    const int id0 = tid, id1 = tid + 256;
    const int lrow0 = id0 >> 2, lc40 = id0 & 3;
    const int lrow1 = id1 >> 2, lc41 = id1 & 3;
    const int so0 = lrow0 * SPAD + lc40 * 8;
    const int so1 = lrow1 * SPAD + lc41 * 8;

    const uint32_t aBase = (uint32_t)(((wm * 64) + (lane & 15)) * SPAD +
                                      (lane >> 4) * 8) * 2;
    const uint32_t bBase = (uint32_t)(((wn * 32) + (lane & 7)) * SPAD +
                                      ((lane >> 3) & 1) * 8) * 2;

    float acc[4][4][4] = {};

    uint4 rAh0, rAh1, rAl0, rAl1, rBh0, rBh1, rBl0, rBl1;
    {
        size_t ga0 = (size_t)(m0 + lrow0) * 128 + lc40;
        size_t ga1 = (size_t)(m0 + lrow1) * 128 + lc41;
        size_t gb0 = (size_t)(n0 + lrow0) * 128 + lc40;
        size_t gb1 = (size_t)(n0 + lrow1) * 128 + lc41;
        rAh0 = ((const uint4*)Ah)[ga0]; rAh1 = ((const uint4*)Ah)[ga1];
        rAl0 = ((const uint4*)Al)[ga0]; rAl1 = ((const uint4*)Al)[ga1];
        rBh0 = ((const uint4*)Bh)[gb0]; rBh1 = ((const uint4*)Bh)[gb1];
        rBl0 = ((const uint4*)Bl)[gb0]; rBl1 = ((const uint4*)Bl)[gb1];
    }
    {   // store chunk 0 into buffer 0
        __nv_bfloat16* p = bufs;
        *(uint4*)&p[so0] = rAh0;               *(uint4*)&p[so1] = rAh1;
        *(uint4*)&p[so0 + 128 * SPAD] = rAl0;  *(uint4*)&p[so1 + 128 * SPAD] = rAl1;
        *(uint4*)&p[so0 + 256 * SPAD] = rBh0;  *(uint4*)&p[so1 + 256 * SPAD] = rBh1;
        *(uint4*)&p[so0 + 384 * SPAD] = rBl0;  *(uint4*)&p[so1 + 384 * SPAD] = rBl1;
    }
    __syncthreads();

    for (int kc = 0; kc < 32; ++kc) {
        if (kc + 1 < 32) {   // prefetch next chunk to regs
            int ko = (kc + 1) * 4;
            size_t ga0 = (size_t)(m0 + lrow0) * 128 + ko + lc40;
            size_t ga1 = (size_t)(m0 + lrow1) * 128 + ko + lc41;
            size_t gb0 = (size_t)(n0 + lrow0) * 128 + ko + lc40;
            size_t gb1 = (size_t)(n0 + lrow1) * 128 + ko + lc41;
            rAh0 = ((const uint4*)Ah)[ga0]; rAh1 = ((const uint4*)Ah)[ga1];
            rAl0 = ((const uint4*)Al)[ga0]; rAl1 = ((const uint4*)Al)[ga1];
            rBh0 = ((const uint4*)Bh)[gb0]; rBh1 = ((const uint4*)Bh)[gb1];
            rBl0 = ((const uint4*)Bl)[gb0]; rBl1 = ((const uint4*)Bl)[gb1];
        }

        const uint32_t bo = (uint32_t)(kc & 1) * (4 * ARR_BYTES);
        const uint32_t uAh = u0 + bo;
        const uint32_t uAl = uAh + ARR_BYTES;
        const uint32_t uBh = uAl + ARR_BYTES;
        const uint32_t uBl = uBh + ARR_BYTES;

        #pragma unroll
        for (int ks = 0; ks < 2; ++ks) {
            const uint32_t kb = (uint32_t)(ks * 16) * 2;
            uint32_t fah[4][4], fal[4][4], fbh[4][2], fbl[4][2];
            #pragma unroll
            for (int mi = 0; mi < 4; ++mi) {
                uint32_t off = aBase + kb + (uint32_t)(mi * 16 * SPAD) * 2;
                ldsm_x4(fah[mi], uAh + off);
                ldsm_x4(fal[mi], uAl + off);
            }
            #pragma unroll
            for (int ni = 0; ni < 4; ++ni) {
                uint32_t off = bBase + kb + (uint32_t)(ni * 8 * SPAD) * 2;
                asm volatile("ldmatrix.sync.aligned.m8n8.x2.shared.b16 {%0,%1}, [%2];"
                    : "=r"(fbh[ni][0]), "=r"(fbh[ni][1]) : "r"(uBh + off));
                asm volatile("ldmatrix.sync.aligned.m8n8.x2.shared.b16 {%0,%1}, [%2];"
                    : "=r"(fbl[ni][0]), "=r"(fbl[ni][1]) : "r"(uBl + off));
            }
            #pragma unroll
            for (int mi = 0; mi < 4; ++mi)
                #pragma unroll
                for (int ni = 0; ni < 4; ++ni) {
                    mma16816(acc[mi][ni], fah[mi], fbh[ni]);
                    mma16816(acc[mi][ni], fah[mi], fbl[ni]);
                    mma16816(acc[mi][ni], fal[mi], fbh[ni]);
                }
        }

        if (kc + 1 < 32) {
            __nv_bfloat16* p = bufs + (size_t)((kc + 1) & 1) * (4 * 128 * SPAD);
            *(uint4*)&p[so0] = rAh0;               *(uint4*)&p[so1] = rAh1;
            *(uint4*)&p[so0 + 128 * SPAD] = rAl0;  *(uint4*)&p[so1 + 128 * SPAD] = rAl1;
            *(uint4*)&p[so0 + 256 * SPAD] = rBh0;  *(uint4*)&p[so1 + 256 * SPAD] = rBh1;
            *(uint4*)&p[so0 + 384 * SPAD] = rBl0;  *(uint4*)&p[so1 + 384 * SPAD] = rBl1;
            __syncthreads();
        }
    }

    // epilogue straight from registers
    #pragma unroll
    for (int mi = 0; mi < 4; ++mi) {
        #pragma unroll
        for (int ni = 0; ni < 4; ++ni) {
            const int col = n0 + wn * 32 + ni * 8 + tig * 2;
            const float bv0 = bias[col], bv1 = bias[col + 1];
            #pragma unroll
            for (int rh = 0; rh < 2; ++rh) {
                const int row = m0 + wm * 64 + mi * 16 + grp + rh * 8;
                float v0 = acc[mi][ni][rh * 2 + 0] + bv0;
                float v1 = acc[mi][ni][rh * 2 + 1] + bv1;
                if (MODE == 0) {
                    const int part = col >> 10;
                    const int h = (col & 1023) >> 6;
                    const int d = col & 63;
                    const int b = row >> 10, l = row & 1023;
                    size_t idx = ((size_t)((b << 4) + h) * 1024 + l) * 64 + d;
                    if (part == 0) {
                        v0 *= 0.125f; v1 *= 0.125f;
                        float2 o = {v0, v1};
                        *(float2*)&g_Q[idx] = o;
                        split2(g_Qhi, g_Qlo, idx, v0, v1);
                    } else if (part == 1) {
                        split2(g_Khi, g_Klo, idx, v0, v1);
                    } else {
                        split2(g_Vhi, g_Vlo, idx, v0, v1);
                    }
                } else {
                    float2 o = {v0, v1};
                    *(float2*)&outp[row * 1024 + col] = o;
                }
            }
        }
    }
}

// ---------------------------------------------------------------------------
// Stage 2: bias_r[row, r] = g_Q[row,:] . rel_pe[r,:]
// ---------------------------------------------------------------------------
__global__ __launch_bounds__(256) void bias_gemm(const float* __restrict__ pe)
{
    __shared__ float pes[129 * 64];
    __shared__ float qs[32 * 64];
    const int tid = threadIdx.x;
    const int row0 = blockIdx.x << 5;
    for (int i = tid; i < 129 * 64; i += 256) pes[i] = pe[i];
    for (int i = tid; i < 32 * 64; i += 256) qs[i] = g_Q[row0 * 64 + i];
    __syncthreads();
    for (int idx = tid; idx < 32 * 129; idx += 256) {
        int r = idx / 129, c = idx - r * 129;
        float s = 0.f;
        #pragma unroll
        for (int d = 0; d < 64; d += 4) {
            float4 a = *(const float4*)&qs[(r << 6) + d];
            float4 p = *(const float4*)&pes[(c << 6) + d];
            s = fmaf(a.x, p.x, s); s = fmaf(a.y, p.y, s);
            s = fmaf(a.z, p.z, s); s = fmaf(a.w, p.w, s);
        }
        g_bias[(row0 + r) * BSTR + c] = s;
    }
}

// ---------------------------------------------------------------------------
// Stage 3: flash attention on mma.sync, split-bf16 (3-term for S and PV).
// Grid (8 i-tiles of 128, 64 bh). 8 warps, each owns 16 i-rows.
// Writes X hi/lo in (b,l,e) layout directly (feeds out-proj GEMM).
// ---------------------------------------------------------------------------
#define AT_SPAD 72
#define AT_ARR (128 * AT_SPAD)
#define ATTN_SMEM (4 * AT_ARR * 2 + 128 * 130 * 4)

__global__ __launch_bounds__(256) void attn_mma()
{
    extern __shared__ __align__(16) char smem_raw[];
    __nv_bfloat16* sKh = (__nv_bfloat16*)smem_raw;
    __nv_bfloat16* sKl = sKh + AT_ARR;
    __nv_bfloat16* sVh = sKl + AT_ARR;
    __nv_bfloat16* sVl = sVh + AT_ARR;
    float* sB = (float*)(sVl + AT_ARR);

    const int bh = blockIdx.y;
    const int i0 = blockIdx.x << 7;
    const int tid = threadIdx.x;
    const int w = tid >> 5, lane = tid & 31;
    const int grp = lane >> 2, tig = lane & 3;

    // bias tile: rows i0..i0+127, 129 cols
    for (int idx = tid; idx < 128 * 129; idx += 256) {
        int r = idx / 129, c = idx - r * 129;
        sB[r * 130 + c] = g_bias[(size_t)(bh * 1024 + i0 + r) * BSTR + c];
    }

    // stage Q tile into sKh/sKl, then ldmatrix A-fragments (kept in regs)
    const size_t qbase = (size_t)bh * 65536 + (size_t)i0 * 64;
    {
        const uint4* srcH = (const uint4*)(g_Qhi + qbase);
        const uint4* srcL = (const uint4*)(g_Qlo + qbase);
        #pragma unroll
        for (int k = 0; k < 4; ++k) {
            int u = tid + k * 256;
            int r = u >> 3, c = (u & 7) * 8;
            *(uint4*)&sKh[r * AT_SPAD + c] = srcH[u];
            *(uint4*)&sKl[r * AT_SPAD + c] = srcL[u];
        }
    }
    __syncthreads();

    uint32_t qh[4][4], ql[4][4];
    {
        const uint32_t uKh = s2u(sKh), uKl = s2u(sKl);
        uint32_t ro = (uint32_t)((w * 16 + (lane & 15)) * AT_SPAD +
                                 (lane >> 4) * 8) * 2;
        #pragma unroll
        for (int ks = 0; ks < 4; ++ks) {
            ldsm_x4(qh[ks], uKh + ro + ks * 32);
            ldsm_x4(ql[ks], uKl + ro + ks * 32);
        }
    }
    __syncthreads();

    float mr[2] = {-1e30f, -1e30f};
    float lr[2] = {0.f, 0.f};
    float o[8][4] = {};

    const uint4* gKh = (const uint4*)(g_Khi + (size_t)bh * 65536);
    const uint4* gKl = (const uint4*)(g_Klo + (size_t)bh * 65536);
    const uint4* gVh = (const uint4*)(g_Vhi + (size_t)bh * 65536);
    const uint4* gVl = (const uint4*)(g_Vlo + (size_t)bh * 65536);
    const uint32_t uKh = s2u(sKh), uKl = s2u(sKl);
    const uint32_t uVh = s2u(sVh), uVl = s2u(sVl);

    const int r0loc = w * 16 + grp;
    const float* brow0 = &sB[r0loc * 130 + 64];
    const float* brow1 = &sB[(r0loc + 8) * 130 + 64];

    for (int j0 = 0; j0 < 1024; j0 += 128) {
        // load K/V hi/lo tiles (contiguous 1024 uint4 each)
        const int ub = j0 * 8;   // uint4 offset (64 bf16 per row = 8 uint4)
        #pragma unroll
        for (int k = 0; k < 4; ++k) {
            int u = tid + k * 256;
            int r = u >> 3, c = (u & 7) * 8;
            int so = r * AT_SPAD + c;
            *(uint4*)&sKh[so] = gKh[ub + u];
            *(uint4*)&sKl[so] = gKl[ub + u];
            *(uint4*)&sVh[so] = gVh[ub + u];
            *(uint4*)&sVl[so] = gVl[ub + u];
        }
        __syncthreads();

        // ---- S = Q K^T (3 terms) ----
        float s[16][4];
        #pragma unroll
        for (int jb = 0; jb < 16; ++jb)
            #pragma unroll
            for (int e = 0; e < 4; ++e) s[jb][e] = 0.f;

        #pragma unroll
        for (int ks = 0; ks < 4; ++ks) {
            #pragma unroll
            for (int jp = 0; jp < 8; ++jp) {
                uint32_t kfh[4], kfl[4];
                uint32_t off = (uint32_t)((jp * 16 + (lane & 7) +
                                           ((lane >> 4) << 3)) * AT_SPAD +
                                          ks * 16 + ((lane >> 3) & 1) * 8) * 2;
                ldsm_x4(kfh, uKh + off);
                ldsm_x4(kfl, uKl + off);
                mma16816(s[2 * jp],     qh[ks], kfh);
                mma16816(s[2 * jp],     qh[ks], kfl);
                mma16816(s[2 * jp],     ql[ks], kfh);
                mma16816(s[2 * jp + 1], qh[ks], kfh + 2);
                mma16816(s[2 * jp + 1], qh[ks], kfl + 2);
                mma16816(s[2 * jp + 1], ql[ks], kfh + 2);
            }
        }

        // ---- relative-PE bias ----
        const int jbase = j0 + tig * 2 - (i0 + r0loc);
        #pragma unroll
        for (int jb = 0; jb < 16; ++jb) {
            int d0 = jbase + jb * 8;
            int dA = min(max(d0,     -64), 64);
            int dB = min(max(d0 + 1, -64), 64);
            int dC = min(max(d0 - 8, -64), 64);
            int dD = min(max(d0 - 7, -64), 64);
            s[jb][0] += brow0[dA];
            s[jb][1] += brow0[dB];
            s[jb][2] += brow1[dC];
            s[jb][3] += brow1[dD];
        }

        // ---- online softmax (rows grp, grp+8) ----
        float mx0 = -1e30f, mx1 = -1e30f;
        #pragma unroll
        for (int jb = 0; jb < 16; ++jb) {
            mx0 = fmaxf(mx0, fmaxf(s[jb][0], s[jb][1]));
            mx1 = fmaxf(mx1, fmaxf(s[jb][2], s[jb][3]));
        }
        mx0 = fmaxf(mx0, __shfl_xor_sync(0xffffffffu, mx0, 1));
        mx0 = fmaxf(mx0, __shfl_xor_sync(0xffffffffu, mx0, 2));
        mx1 = fmaxf(mx1, __shfl_xor_sync(0xffffffffu, mx1, 1));
        mx1 = fmaxf(mx1, __shfl_xor_sync(0xffffffffu, mx1, 2));
        float nm0 = fmaxf(mr[0], mx0), nm1 = fmaxf(mr[1], mx1);
        float sc0 = __expf(mr[0] - nm0), sc1 = __expf(mr[1] - nm1);
        float ps0 = 0.f, ps1 = 0.f;
        #pragma unroll
        for (int jb = 0; jb < 16; ++jb) {
            s[jb][0] = __expf(s[jb][0] - nm0);
            s[jb][1] = __expf(s[jb][1] - nm0);
            s[jb][2] = __expf(s[jb][2] - nm1);
            s[jb][3] = __expf(s[jb][3] - nm1);
            ps0 += s[jb][0] + s[jb][1];
            ps1 += s[jb][2] + s[jb][3];
        }
        ps0 += __shfl_xor_sync(0xffffffffu, ps0, 1);
        ps0 += __shfl_xor_sync(0xffffffffu, ps0, 2);
        ps1 += __shfl_xor_sync(0xffffffffu, ps1, 1);
        ps1 += __shfl_xor_sync(0xffffffffu, ps1, 2);
        lr[0] = lr[0] * sc0 + ps0; mr[0] = nm0;
        lr[1] = lr[1] * sc1 + ps1; mr[1] = nm1;
        #pragma unroll
        for (int nd = 0; nd < 8; ++nd) {
            o[nd][0] *= sc0; o[nd][1] *= sc0;
            o[nd][2] *= sc1; o[nd][3] *= sc1;
        }

        // ---- O += P V (3 terms, P from registers) ----
        #pragma unroll
        for (int kk = 0; kk < 8; ++kk) {
            uint32_t ah[4], al[4];
            pack_hl(s[2 * kk][0],     s[2 * kk][1],     ah[0], al[0]);
            pack_hl(s[2 * kk][2],     s[2 * kk][3],     ah[1], al[1]);
            pack_hl(s[2 * kk + 1][0], s[2 * kk + 1][1], ah[2], al[2]);
            pack_hl(s[2 * kk + 1][2], s[2 * kk + 1][3], ah[3], al[3]);
            #pragma unroll
            for (int np = 0; np < 4; ++np) {
                uint32_t vfh[4], vfl[4];
                uint32_t off = (uint32_t)((kk * 16 + (lane & 7) +
                                           ((lane >> 3) & 1) * 8) * AT_SPAD +
                                          np * 16 + (lane >> 4) * 8) * 2;
                ldsm_x4_t(vfh, uVh + off);
                ldsm_x4_t(vfl, uVl + off);
                mma16816(o[2 * np],     ah, vfh);
                mma16816(o[2 * np],     ah, vfl);
                mma16816(o[2 * np],     al, vfh);
                mma16816(o[2 * np + 1], ah, vfh + 2);
                mma16816(o[2 * np + 1], ah, vfl + 2);
                mma16816(o[2 * np + 1], al, vfh + 2);
            }
        }
        __syncthreads();
    }

    // ---- finalize + write X hi/lo in (b,l,e) layout ----
    const float inv0 = 1.0f / lr[0], inv1 = 1.0f / lr[1];
    const int b = bh >> 4, h = bh & 15;
    const size_t row0 = (size_t)(b * 1024 + i0 + r0loc);
    const size_t row1 = row0 + 8;
    #pragma unroll
    for (int nd = 0; nd < 8; ++nd) {
        const int col = h * 64 + nd * 8 + tig * 2;
        uint32_t hi, lo;
        pack_hl(o[nd][0] * inv0, o[nd][1] * inv0, hi, lo);
        *(uint32_t*)&g_Xhi[row0 * 1024 + col] = hi;
        *(uint32_t*)&g_Xlo[row0 * 1024 + col] = lo;
        pack_hl(o[nd][2] * inv1, o[nd][3] * inv1, hi, lo);
        *(uint32_t*)&g_Xhi[row1 * 1024 + col] = hi;
        *(uint32_t*)&g_Xlo[row1 * 1024 + col] = lo;
    }
}

// ---------------------------------------------------------------------------
extern "C" void kernel_launch(void* const* d_in, const int* in_sizes, int n_in,
                              void* d_out, int out_size)
{
    const float* q  = (const float*)d_in[0];
    const float* w3 = (const float*)d_in[1];
    const float* b3 = (const float*)d_in[2];
    const float* ow = (const float*)d_in[3];
    const float* ob = (const float*)d_in[4];
    const float* pe = (const float*)d_in[5];
    float* out = (float*)d_out;

    cudaFuncSetAttribute(attn_mma, cudaFuncAttributeMaxDynamicSharedMemorySize,
                         ATTN_SMEM);
    cudaFuncSetAttribute(mma_gemm<0>, cudaFuncAttributeMaxDynamicSharedMemorySize,
                         GEMM_SMEM);
    cudaFuncSetAttribute(mma_gemm<1>, cudaFuncAttributeMaxDynamicSharedMemorySize,
                         GEMM_SMEM);

    split_kernel<<<4096, 256>>>(q,  4096 * 1024 / 4, 0);
    split_kernel<<<3072, 256>>>(w3, 3072 * 1024 / 4, 1);
    split_kernel<<<1024, 256>>>(ow, 1024 * 1024 / 4, 2);

    mma_gemm<0><<<dim3(24, 32), 256, GEMM_SMEM>>>(b3, nullptr);
    bias_gemm<<<2048, 256>>>(pe);
    attn_mma<<<dim3(8, 64), 256, ATTN_SMEM>>>();
    mma_gemm<1><<<dim3(8, 32), 256, GEMM_SMEM>>>(ob, out);
}

// round 6
// speedup vs baseline: 1.9838x; 1.0760x over previous
#include <cuda_runtime.h>
#include <cuda_bf16.h>
#include <cstdint>

// ---------------------------------------------------------------------------
// RelativeSelfAttention: B=4, L=1024, E=1024, H=16, D=64, K=64 (129 PE rows)
// R6: cp.async double-buffered pipelines, 2 CTAs/SM on the GEMMs
// ---------------------------------------------------------------------------

#define NBH   64
#define BSTR  132

__device__ float g_Q[NBH * 1024 * 64];          // scaled fp32 Q (for bias_gemm)
__device__ float g_bias[NBH * 1024 * BSTR];

__device__ __nv_bfloat16 g_Ahi[4096 * 1024], g_Alo[4096 * 1024];
__device__ __nv_bfloat16 g_Whi[3072 * 1024], g_Wlo[3072 * 1024];
__device__ __nv_bfloat16 g_OWhi[1024 * 1024], g_OWlo[1024 * 1024];
__device__ __nv_bfloat16 g_Xhi[4096 * 1024], g_Xlo[4096 * 1024];
__device__ __nv_bfloat16 g_Qhi[NBH * 65536], g_Qlo[NBH * 65536];
__device__ __nv_bfloat16 g_Khi[NBH * 65536], g_Klo[NBH * 65536];
__device__ __nv_bfloat16 g_Vhi[NBH * 65536], g_Vlo[NBH * 65536];

// ------------------------------- PTX helpers -------------------------------
__device__ __forceinline__ uint32_t s2u(const void* p) {
    return (uint32_t)__cvta_generic_to_shared(p);
}
__device__ __forceinline__ void ldsm_x4(uint32_t* r, uint32_t addr) {
    asm volatile("ldmatrix.sync.aligned.m8n8.x4.shared.b16 {%0,%1,%2,%3}, [%4];"
        : "=r"(r[0]), "=r"(r[1]), "=r"(r[2]), "=r"(r[3]) : "r"(addr));
}
__device__ __forceinline__ void ldsm_x4_t(uint32_t* r, uint32_t addr) {
    asm volatile("ldmatrix.sync.aligned.m8n8.x4.trans.shared.b16 {%0,%1,%2,%3}, [%4];"
        : "=r"(r[0]), "=r"(r[1]), "=r"(r[2]), "=r"(r[3]) : "r"(addr));
}
__device__ __forceinline__ void mma16816(float* c, const uint32_t* a,
                                         const uint32_t* b) {
    asm volatile(
        "mma.sync.aligned.m16n8k16.row.col.f32.bf16.bf16.f32 "
        "{%0,%1,%2,%3}, {%4,%5,%6,%7}, {%8,%9}, {%0,%1,%2,%3};"
        : "+f"(c[0]), "+f"(c[1]), "+f"(c[2]), "+f"(c[3])
        : "r"(a[0]), "r"(a[1]), "r"(a[2]), "r"(a[3]), "r"(b[0]), "r"(b[1]));
}
__device__ __forceinline__ void cpa16(uint32_t dst, const void* src) {
    asm volatile("cp.async.cg.shared.global [%0], [%1], 16;"
                 :: "r"(dst), "l"(src) : "memory");
}
__device__ __forceinline__ void cpa_commit() {
    asm volatile("cp.async.commit_group;" ::: "memory");
}
template <int N>
__device__ __forceinline__ void cpa_wait() {
    asm volatile("cp.async.wait_group %0;" :: "n"(N) : "memory");
}
// pack (v0,v1) into bf16x2 hi + bf16x2 lo-residual
__device__ __forceinline__ void pack_hl(float v0, float v1,
                                        uint32_t& hi, uint32_t& lo) {
    __nv_bfloat16 h0 = __float2bfloat16(v0), h1 = __float2bfloat16(v1);
    float l0 = v0 - __bfloat162float(h0), l1 = v1 - __bfloat162float(h1);
    __nv_bfloat162 H; H.x = h0; H.y = h1;
    __nv_bfloat162 L; L.x = __float2bfloat16(l0); L.y = __float2bfloat16(l1);
    hi = *(uint32_t*)&H; lo = *(uint32_t*)&L;
}
__device__ __forceinline__ void split2(__nv_bfloat16* hp, __nv_bfloat16* lp,
                                       size_t idx, float v0, float v1) {
    uint32_t hi, lo;
    pack_hl(v0, v1, hi, lo);
    *(uint32_t*)&hp[idx] = hi;
    *(uint32_t*)&lp[idx] = lo;
}

// ---------------------------------------------------------------------------
// fp32 -> bf16 hi/lo split (which: 0=A(q), 1=W3, 2=out_w)
// ---------------------------------------------------------------------------
__global__ __launch_bounds__(256) void split_kernel(
    const float* __restrict__ src, int n4, int which)
{
    int i = blockIdx.x * 256 + threadIdx.x;
    if (i >= n4) return;
    float4 v = ((const float4*)src)[i];
    __nv_bfloat16 h[4], l[4];
    float f[4] = {v.x, v.y, v.z, v.w};
    #pragma unroll
    for (int k = 0; k < 4; ++k) {
        h[k] = __float2bfloat16(f[k]);
        l[k] = __float2bfloat16(f[k] - __bfloat162float(h[k]));
    }
    __nv_bfloat16* hp = which == 0 ? g_Ahi : (which == 1 ? g_Whi : g_OWhi);
    __nv_bfloat16* lp = which == 0 ? g_Alo : (which == 1 ? g_Wlo : g_OWlo);
    *(uint2*)&hp[i * 4] = *(uint2*)h;
    *(uint2*)&lp[i * 4] = *(uint2*)l;
}

// ---------------------------------------------------------------------------
// Split-bf16 mma.sync GEMM, cp.async double-buffered, 2 CTAs/SM.
// MODE 0: A=q-split,B=W3-split -> g_Q fp32 (x0.125) + Q/K/V bf16-split
// MODE 1: A=X-split,B=out_w-split -> outp
// CTA tile 128x128, 8 warps (2m x 4n), warp tile 64x32, K-chunk 32.
// Stage: 4 arrays x 128 rows x SPAD(40) bf16 = 40960 B; 2 stages = 80 KB.
// ---------------------------------------------------------------------------
#define SPAD 40
#define ARR_B 10240
#define STG_B (4 * ARR_B)
#define GEMM_SMEM (2 * STG_B)

template <int MODE>
__global__ __launch_bounds__(256, 2) void mma_gemm(
    const float* __restrict__ bias, float* __restrict__ outp)
{
    extern __shared__ __align__(16) char gsm[];
    const uint32_t u0 = s2u(gsm);

    const __nv_bfloat16* Ah = (MODE == 0) ? g_Ahi : g_Xhi;
    const __nv_bfloat16* Al = (MODE == 0) ? g_Alo : g_Xlo;
    const __nv_bfloat16* Bh = (MODE == 0) ? g_Whi : g_OWhi;
    const __nv_bfloat16* Bl = (MODE == 0) ? g_Wlo : g_OWlo;

    const int m0 = blockIdx.y << 7;
    const int n0 = blockIdx.x << 7;
    const int tid = threadIdx.x;
    const int wid = tid >> 5, lane = tid & 31;
    const int wm = wid >> 2, wn = wid & 3;
    const int grp = lane >> 2, tig = lane & 3;

    // loader geometry: 512 uint4 per array per chunk, 2 per thread
    const int lrow0 = tid >> 2,        lc40 = tid & 3;
    const int lrow1 = (tid + 256) >> 2, lc41 = (tid + 256) & 3;
    const uint32_t sb0 = (uint32_t)(lrow0 * SPAD + lc40 * 8) * 2;  // bytes
    const uint32_t sb1 = (uint32_t)(lrow1 * SPAD + lc41 * 8) * 2;

    const uint32_t aBase = (uint32_t)(((wm * 64) + (lane & 15)) * SPAD +
                                      (lane >> 4) * 8) * 2;
    const uint32_t bBase = (uint32_t)(((wn * 32) + (lane & 7)) * SPAD +
                                      ((lane >> 3) & 1) * 8) * 2;

    float acc[4][4][4] = {};

    // async-issue one K-chunk into a stage
    auto issue = [&](int stage, int kc) {
        const int ko = kc * 4;
        const size_t ga0 = (size_t)(m0 + lrow0) * 128 + ko + lc40;
        const size_t ga1 = (size_t)(m0 + lrow1) * 128 + ko + lc41;
        const size_t gb0 = (size_t)(n0 + lrow0) * 128 + ko + lc40;
        const size_t gb1 = (size_t)(n0 + lrow1) * 128 + ko + lc41;
        const uint32_t s = u0 + (uint32_t)stage * STG_B;
        cpa16(s + sb0,             (const uint4*)Ah + ga0);
        cpa16(s + sb1,             (const uint4*)Ah + ga1);
        cpa16(s + ARR_B + sb0,     (const uint4*)Al + ga0);
        cpa16(s + ARR_B + sb1,     (const uint4*)Al + ga1);
        cpa16(s + 2 * ARR_B + sb0, (const uint4*)Bh + gb0);
        cpa16(s + 2 * ARR_B + sb1, (const uint4*)Bh + gb1);
        cpa16(s + 3 * ARR_B + sb0, (const uint4*)Bl + gb0);
        cpa16(s + 3 * ARR_B + sb1, (const uint4*)Bl + gb1);
        cpa_commit();
    };

    issue(0, 0);
    issue(1, 1);

    for (int kc = 0; kc < 32; ++kc) {
        cpa_wait<1>();
        __syncthreads();

        const uint32_t uAh = u0 + (uint32_t)(kc & 1) * STG_B;
        const uint32_t uAl = uAh + ARR_B;
        const uint32_t uBh = uAl + ARR_B;
        const uint32_t uBl = uBh + ARR_B;

        #pragma unroll
        for (int ks = 0; ks < 2; ++ks) {
            const uint32_t kb = (uint32_t)(ks * 16) * 2;
            uint32_t fbh[4][2], fbl[4][2];
            #pragma unroll
            for (int ni = 0; ni < 4; ++ni) {
                uint32_t off = bBase + kb + (uint32_t)(ni * 8 * SPAD) * 2;
                asm volatile("ldmatrix.sync.aligned.m8n8.x2.shared.b16 {%0,%1}, [%2];"
                    : "=r"(fbh[ni][0]), "=r"(fbh[ni][1]) : "r"(uBh + off));
                asm volatile("ldmatrix.sync.aligned.m8n8.x2.shared.b16 {%0,%1}, [%2];"
                    : "=r"(fbl[ni][0]), "=r"(fbl[ni][1]) : "r"(uBl + off));
            }
            #pragma unroll
            for (int mi = 0; mi < 4; ++mi) {
                uint32_t fah[4], fal[4];
                uint32_t off = aBase + kb + (uint32_t)(mi * 16 * SPAD) * 2;
                ldsm_x4(fah, uAh + off);
                ldsm_x4(fal, uAl + off);
                #pragma unroll
                for (int ni = 0; ni < 4; ++ni) {
                    mma16816(acc[mi][ni], fah, fbh[ni]);
                    mma16816(acc[mi][ni], fah, fbl[ni]);
                    mma16816(acc[mi][ni], fal, fbh[ni]);
                }
            }
        }
        __syncthreads();
        if (kc + 2 < 32) issue(kc & 1, kc + 2);
    }

    // epilogue straight from registers
    #pragma unroll
    for (int mi = 0; mi < 4; ++mi) {
        #pragma unroll
        for (int ni = 0; ni < 4; ++ni) {
            const int col = n0 + wn * 32 + ni * 8 + tig * 2;
            const float bv0 = bias[col], bv1 = bias[col + 1];
            #pragma unroll
            for (int rh = 0; rh < 2; ++rh) {
                const int row = m0 + wm * 64 + mi * 16 + grp + rh * 8;
                float v0 = acc[mi][ni][rh * 2 + 0] + bv0;
                float v1 = acc[mi][ni][rh * 2 + 1] + bv1;
                if (MODE == 0) {
                    const int part = col >> 10;
                    const int h = (col & 1023) >> 6;
                    const int d = col & 63;
                    const int b = row >> 10, l = row & 1023;
                    size_t idx = ((size_t)((b << 4) + h) * 1024 + l) * 64 + d;
                    if (part == 0) {
                        v0 *= 0.125f; v1 *= 0.125f;
                        float2 o = {v0, v1};
                        *(float2*)&g_Q[idx] = o;
                        split2(g_Qhi, g_Qlo, idx, v0, v1);
                    } else if (part == 1) {
                        split2(g_Khi, g_Klo, idx, v0, v1);
                    } else {
                        split2(g_Vhi, g_Vlo, idx, v0, v1);
                    }
                } else {
                    float2 o = {v0, v1};
                    *(float2*)&outp[row * 1024 + col] = o;
                }
            }
        }
    }
}

// ---------------------------------------------------------------------------
// Stage 2: bias_r[row, r] = g_Q[row,:] . rel_pe[r,:]
// ---------------------------------------------------------------------------
__global__ __launch_bounds__(256) void bias_gemm(const float* __restrict__ pe)
{
    __shared__ float pes[129 * 64];
    __shared__ float qs[32 * 64];
    const int tid = threadIdx.x;
    const int row0 = blockIdx.x << 5;
    for (int i = tid; i < 129 * 64; i += 256) pes[i] = pe[i];
    for (int i = tid; i < 32 * 64; i += 256) qs[i] = g_Q[row0 * 64 + i];
    __syncthreads();
    for (int idx = tid; idx < 32 * 129; idx += 256) {
        int r = idx / 129, c = idx - r * 129;
        float s = 0.f;
        #pragma unroll
        for (int d = 0; d < 64; d += 4) {
            float4 a = *(const float4*)&qs[(r << 6) + d];
            float4 p = *(const float4*)&pes[(c << 6) + d];
            s = fmaf(a.x, p.x, s); s = fmaf(a.y, p.y, s);
            s = fmaf(a.z, p.z, s); s = fmaf(a.w, p.w, s);
        }
        g_bias[(row0 + r) * BSTR + c] = s;
    }
}

// ---------------------------------------------------------------------------
// Stage 3: flash attention on mma.sync, cp.async double-buffered K/V tiles.
// Grid (8 i-tiles of 128, 64 bh). 8 warps, each owns 16 i-rows.
// smem: 2 stages x (4 arrays x 128 x 72 bf16 = 73728 B) + bias 66560 B.
// ---------------------------------------------------------------------------
#define AT_SPAD 72
#define AT_ARR_B (128 * AT_SPAD * 2)      // 18432
#define AT_STG_B (4 * AT_ARR_B)           // 73728
#define ATTN_SMEM (2 * AT_STG_B + 128 * 130 * 4)

__global__ __launch_bounds__(256) void attn_mma()
{
    extern __shared__ __align__(16) char smem_raw[];
    const uint32_t u0 = s2u(smem_raw);
    float* sB = (float*)(smem_raw + 2 * AT_STG_B);

    const int bh = blockIdx.y;
    const int i0 = blockIdx.x << 7;
    const int tid = threadIdx.x;
    const int w = tid >> 5, lane = tid & 31;
    const int grp = lane >> 2, tig = lane & 3;

    const uint4* gKh = (const uint4*)(g_Khi + (size_t)bh * 65536);
    const uint4* gKl = (const uint4*)(g_Klo + (size_t)bh * 65536);
    const uint4* gVh = (const uint4*)(g_Vhi + (size_t)bh * 65536);
    const uint4* gVl = (const uint4*)(g_Vlo + (size_t)bh * 65536);

    // stage Q tile into stage-0 buffers (plain stores), grab A-fragments
    const size_t qbase = (size_t)bh * 65536 + (size_t)i0 * 64;
    {
        const uint4* srcH = (const uint4*)(g_Qhi + qbase);
        const uint4* srcL = (const uint4*)(g_Qlo + qbase);
        __nv_bfloat16* t0 = (__nv_bfloat16*)smem_raw;
        __nv_bfloat16* t1 = (__nv_bfloat16*)(smem_raw + AT_ARR_B);
        #pragma unroll
        for (int k = 0; k < 4; ++k) {
            int u = tid + k * 256;
            int r = u >> 3, c = (u & 7) * 8;
            *(uint4*)&t0[r * AT_SPAD + c] = srcH[u];
            *(uint4*)&t1[r * AT_SPAD + c] = srcL[u];
        }
    }
    __syncthreads();

    uint32_t qh[4][4], ql[4][4];
    {
        uint32_t ro = (uint32_t)((w * 16 + (lane & 15)) * AT_SPAD +
                                 (lane >> 4) * 8) * 2;
        #pragma unroll
        for (int ks = 0; ks < 4; ++ks) {
            ldsm_x4(qh[ks], u0 + ro + ks * 32);
            ldsm_x4(ql[ks], u0 + AT_ARR_B + ro + ks * 32);
        }
    }
    __syncthreads();

    // issue K/V tile jt into stage
    auto issue_kv = [&](int stage, int jt) {
        const int ub = jt * 1024;          // uint4 offset of tile
        const uint32_t s = u0 + (uint32_t)stage * AT_STG_B;
        #pragma unroll
        for (int k = 0; k < 4; ++k) {
            int u = tid + k * 256;
            uint32_t dst = s + (uint32_t)(u >> 3) * (AT_SPAD * 2) +
                           (uint32_t)(u & 7) * 16;
            cpa16(dst,                gKh + ub + u);
            cpa16(dst + AT_ARR_B,     gKl + ub + u);
            cpa16(dst + 2 * AT_ARR_B, gVh + ub + u);
            cpa16(dst + 3 * AT_ARR_B, gVl + ub + u);
        }
        cpa_commit();
    };

    issue_kv(0, 0);

    // bias tile: rows i0..i0+127, 129 cols (overlaps with first cp.async)
    for (int idx = tid; idx < 128 * 129; idx += 256) {
        int r = idx / 129, c = idx - r * 129;
        sB[r * 130 + c] = g_bias[(size_t)(bh * 1024 + i0 + r) * BSTR + c];
    }

    float mr[2] = {-1e30f, -1e30f};
    float lr[2] = {0.f, 0.f};
    float o[8][4] = {};

    const int r0loc = w * 16 + grp;
    const float* brow0 = &sB[r0loc * 130 + 64];
    const float* brow1 = &sB[(r0loc + 8) * 130 + 64];

    for (int jt = 0; jt < 8; ++jt) {
        if (jt + 1 < 8) issue_kv((jt + 1) & 1, jt + 1);
        cpa_wait<1>();
        __syncthreads();

        const uint32_t uKh = u0 + (uint32_t)(jt & 1) * AT_STG_B;
        const uint32_t uKl = uKh + AT_ARR_B;
        const uint32_t uVh = uKl + AT_ARR_B;
        const uint32_t uVl = uVh + AT_ARR_B;
        const int j0 = jt << 7;

        // ---- S = Q K^T (3 terms) ----
        float s[16][4];
        #pragma unroll
        for (int jb = 0; jb < 16; ++jb)
            #pragma unroll
            for (int e = 0; e < 4; ++e) s[jb][e] = 0.f;

        #pragma unroll
        for (int ks = 0; ks < 4; ++ks) {
            #pragma unroll
            for (int jp = 0; jp < 8; ++jp) {
                uint32_t kfh[4], kfl[4];
                uint32_t off = (uint32_t)((jp * 16 + (lane & 7) +
                                           ((lane >> 4) << 3)) * AT_SPAD +
                                          ks * 16 + ((lane >> 3) & 1) * 8) * 2;
                ldsm_x4(kfh, uKh + off);
                ldsm_x4(kfl, uKl + off);
                mma16816(s[2 * jp],     qh[ks], kfh);
                mma16816(s[2 * jp],     qh[ks], kfl);
                mma16816(s[2 * jp],     ql[ks], kfh);
                mma16816(s[2 * jp + 1], qh[ks], kfh + 2);
                mma16816(s[2 * jp + 1], qh[ks], kfl + 2);
                mma16816(s[2 * jp + 1], ql[ks], kfh + 2);
            }
        }

        // ---- relative-PE bias ----
        const int jbase = j0 + tig * 2 - (i0 + r0loc);
        #pragma unroll
        for (int jb = 0; jb < 16; ++jb) {
            int d0 = jbase + jb * 8;
            int dA = min(max(d0,     -64), 64);
            int dB = min(max(d0 + 1, -64), 64);
            int dC = min(max(d0 - 8, -64), 64);
            int dD = min(max(d0 - 7, -64), 64);
            s[jb][0] += brow0[dA];
            s[jb][1] += brow0[dB];
            s[jb][2] += brow1[dC];
            s[jb][3] += brow1[dD];
        }

        // ---- online softmax ----
        float mx0 = -1e30f, mx1 = -1e30f;
        #pragma unroll
        for (int jb = 0; jb < 16; ++jb) {
            mx0 = fmaxf(mx0, fmaxf(s[jb][0], s[jb][1]));
            mx1 = fmaxf(mx1, fmaxf(s[jb][2], s[jb][3]));
        }
        mx0 = fmaxf(mx0, __shfl_xor_sync(0xffffffffu, mx0, 1));
        mx0 = fmaxf(mx0, __shfl_xor_sync(0xffffffffu, mx0, 2));
        mx1 = fmaxf(mx1, __shfl_xor_sync(0xffffffffu, mx1, 1));
        mx1 = fmaxf(mx1, __shfl_xor_sync(0xffffffffu, mx1, 2));
        float nm0 = fmaxf(mr[0], mx0), nm1 = fmaxf(mr[1], mx1);
        float sc0 = __expf(mr[0] - nm0), sc1 = __expf(mr[1] - nm1);
        float ps0 = 0.f, ps1 = 0.f;
        #pragma unroll
        for (int jb = 0; jb < 16; ++jb) {
            s[jb][0] = __expf(s[jb][0] - nm0);
            s[jb][1] = __expf(s[jb][1] - nm0);
            s[jb][2] = __expf(s[jb][2] - nm1);
            s[jb][3] = __expf(s[jb][3] - nm1);
            ps0 += s[jb][0] + s[jb][1];
            ps1 += s[jb][2] + s[jb][3];
        }
        ps0 += __shfl_xor_sync(0xffffffffu, ps0, 1);
        ps0 += __shfl_xor_sync(0xffffffffu, ps0, 2);
        ps1 += __shfl_xor_sync(0xffffffffu, ps1, 1);
        ps1 += __shfl_xor_sync(0xffffffffu, ps1, 2);
        lr[0] = lr[0] * sc0 + ps0; mr[0] = nm0;
        lr[1] = lr[1] * sc1 + ps1; mr[1] = nm1;
        #pragma unroll
        for (int nd = 0; nd < 8; ++nd) {
            o[nd][0] *= sc0; o[nd][1] *= sc0;
            o[nd][2] *= sc1; o[nd][3] *= sc1;
        }

        // ---- O += P V (3 terms, P from registers) ----
        #pragma unroll
        for (int kk = 0; kk < 8; ++kk) {
            uint32_t ah[4], al[4];
            pack_hl(s[2 * kk][0],     s[2 * kk][1],     ah[0], al[0]);
            pack_hl(s[2 * kk][2],     s[2 * kk][3],     ah[1], al[1]);
            pack_hl(s[2 * kk + 1][0], s[2 * kk + 1][1], ah[2], al[2]);
            pack_hl(s[2 * kk + 1][2], s[2 * kk + 1][3], ah[3], al[3]);
            #pragma unroll
            for (int np = 0; np < 4; ++np) {
                uint32_t vfh[4], vfl[4];
                uint32_t off = (uint32_t)((kk * 16 + (lane & 7) +
                                           ((lane >> 3) & 1) * 8) * AT_SPAD +
                                          np * 16 + (lane >> 4) * 8) * 2;
                ldsm_x4_t(vfh, uVh + off);
                ldsm_x4_t(vfl, uVl + off);
                mma16816(o[2 * np],     ah, vfh);
                mma16816(o[2 * np],     ah, vfl);
                mma16816(o[2 * np],     al, vfh);
                mma16816(o[2 * np + 1], ah, vfh + 2);
                mma16816(o[2 * np + 1], ah, vfl + 2);
                mma16816(o[2 * np + 1], al, vfh + 2);
            }
        }
        __syncthreads();
    }

    // ---- finalize + write X hi/lo in (b,l,e) layout ----
    const float inv0 = 1.0f / lr[0], inv1 = 1.0f / lr[1];
    const int b = bh >> 4, h = bh & 15;
    const size_t row0 = (size_t)(b * 1024 + i0 + r0loc);
    const size_t row1 = row0 + 8;
    #pragma unroll
    for (int nd = 0; nd < 8; ++nd) {
        const int col = h * 64 + nd * 8 + tig * 2;
        uint32_t hi, lo;
        pack_hl(o[nd][0] * inv0, o[nd][1] * inv0, hi, lo);
        *(uint32_t*)&g_Xhi[row0 * 1024 + col] = hi;
        *(uint32_t*)&g_Xlo[row0 * 1024 + col] = lo;
        pack_hl(o[nd][2] * inv1, o[nd][3] * inv1, hi, lo);
        *(uint32_t*)&g_Xhi[row1 * 1024 + col] = hi;
        *(uint32_t*)&g_Xlo[row1 * 1024 + col] = lo;
    }
}

// ---------------------------------------------------------------------------
extern "C" void kernel_launch(void* const* d_in, const int* in_sizes, int n_in,
                              void* d_out, int out_size)
{
    const float* q  = (const float*)d_in[0];
    const float* w3 = (const float*)d_in[1];
    const float* b3 = (const float*)d_in[2];
    const float* ow = (const float*)d_in[3];
    const float* ob = (const float*)d_in[4];
    const float* pe = (const float*)d_in[5];
    float* out = (float*)d_out;

    cudaFuncSetAttribute(attn_mma, cudaFuncAttributeMaxDynamicSharedMemorySize,
                         ATTN_SMEM);
    cudaFuncSetAttribute(mma_gemm<0>, cudaFuncAttributeMaxDynamicSharedMemorySize,
                         GEMM_SMEM);
    cudaFuncSetAttribute(mma_gemm<1>, cudaFuncAttributeMaxDynamicSharedMemorySize,
                         GEMM_SMEM);

    split_kernel<<<4096, 256>>>(q,  4096 * 1024 / 4, 0);
    split_kernel<<<3072, 256>>>(w3, 3072 * 1024 / 4, 1);
    split_kernel<<<1024, 256>>>(ow, 1024 * 1024 / 4, 2);

    mma_gemm<0><<<dim3(24, 32), 256, GEMM_SMEM>>>(b3, nullptr);
    bias_gemm<<<2048, 256>>>(pe);
    attn_mma<<<dim3(8, 64), 256, ATTN_SMEM>>>();
    mma_gemm<1><<<dim3(8, 32), 256, GEMM_SMEM>>>(ob, out);
}

// round 8
// speedup vs baseline: 2.0251x; 1.0208x over previous
#include <cuda_runtime.h>
#include <cuda_bf16.h>
#include <cstdint>

// ---------------------------------------------------------------------------
// RelativeSelfAttention: B=4, L=1024, E=1024, H=16, D=64, K=64 (129 PE rows)
// R8: R7 attention (2 CTAs/SM, j-tile 64, K/V ping-pong) with fixed loader
// ---------------------------------------------------------------------------

#define NBH   64
#define BSTR  132

__device__ float g_Q[NBH * 1024 * 64];          // scaled fp32 Q (for bias_gemm)
__device__ float g_bias[NBH * 1024 * BSTR];

__device__ __nv_bfloat16 g_Ahi[4096 * 1024], g_Alo[4096 * 1024];
__device__ __nv_bfloat16 g_Whi[3072 * 1024], g_Wlo[3072 * 1024];
__device__ __nv_bfloat16 g_OWhi[1024 * 1024], g_OWlo[1024 * 1024];
__device__ __nv_bfloat16 g_Xhi[4096 * 1024], g_Xlo[4096 * 1024];
__device__ __nv_bfloat16 g_Qhi[NBH * 65536], g_Qlo[NBH * 65536];
__device__ __nv_bfloat16 g_Khi[NBH * 65536], g_Klo[NBH * 65536];
__device__ __nv_bfloat16 g_Vhi[NBH * 65536], g_Vlo[NBH * 65536];

// ------------------------------- PTX helpers -------------------------------
__device__ __forceinline__ uint32_t s2u(const void* p) {
    return (uint32_t)__cvta_generic_to_shared(p);
}
__device__ __forceinline__ void ldsm_x4(uint32_t* r, uint32_t addr) {
    asm volatile("ldmatrix.sync.aligned.m8n8.x4.shared.b16 {%0,%1,%2,%3}, [%4];"
        : "=r"(r[0]), "=r"(r[1]), "=r"(r[2]), "=r"(r[3]) : "r"(addr));
}
__device__ __forceinline__ void ldsm_x4_t(uint32_t* r, uint32_t addr) {
    asm volatile("ldmatrix.sync.aligned.m8n8.x4.trans.shared.b16 {%0,%1,%2,%3}, [%4];"
        : "=r"(r[0]), "=r"(r[1]), "=r"(r[2]), "=r"(r[3]) : "r"(addr));
}
__device__ __forceinline__ void mma16816(float* c, const uint32_t* a,
                                         const uint32_t* b) {
    asm volatile(
        "mma.sync.aligned.m16n8k16.row.col.f32.bf16.bf16.f32 "
        "{%0,%1,%2,%3}, {%4,%5,%6,%7}, {%8,%9}, {%0,%1,%2,%3};"
        : "+f"(c[0]), "+f"(c[1]), "+f"(c[2]), "+f"(c[3])
        : "r"(a[0]), "r"(a[1]), "r"(a[2]), "r"(a[3]), "r"(b[0]), "r"(b[1]));
}
__device__ __forceinline__ void cpa16(uint32_t dst, const void* src) {
    asm volatile("cp.async.cg.shared.global [%0], [%1], 16;"
                 :: "r"(dst), "l"(src) : "memory");
}
__device__ __forceinline__ void cpa_commit() {
    asm volatile("cp.async.commit_group;" ::: "memory");
}
template <int N>
__device__ __forceinline__ void cpa_wait() {
    asm volatile("cp.async.wait_group %0;" :: "n"(N) : "memory");
}
__device__ __forceinline__ void pack_hl(float v0, float v1,
                                        uint32_t& hi, uint32_t& lo) {
    __nv_bfloat16 h0 = __float2bfloat16(v0), h1 = __float2bfloat16(v1);
    float l0 = v0 - __bfloat162float(h0), l1 = v1 - __bfloat162float(h1);
    __nv_bfloat162 H; H.x = h0; H.y = h1;
    __nv_bfloat162 L; L.x = __float2bfloat16(l0); L.y = __float2bfloat16(l1);
    hi = *(uint32_t*)&H; lo = *(uint32_t*)&L;
}
__device__ __forceinline__ void split2(__nv_bfloat16* hp, __nv_bfloat16* lp,
                                       size_t idx, float v0, float v1) {
    uint32_t hi, lo;
    pack_hl(v0, v1, hi, lo);
    *(uint32_t*)&hp[idx] = hi;
    *(uint32_t*)&lp[idx] = lo;
}

// ---------------------------------------------------------------------------
// fp32 -> bf16 hi/lo split (which: 0=A(q), 1=W3, 2=out_w)
// ---------------------------------------------------------------------------
__global__ __launch_bounds__(256) void split_kernel(
    const float* __restrict__ src, int n4, int which)
{
    int i = blockIdx.x * 256 + threadIdx.x;
    if (i >= n4) return;
    float4 v = ((const float4*)src)[i];
    __nv_bfloat16 h[4], l[4];
    float f[4] = {v.x, v.y, v.z, v.w};
    #pragma unroll
    for (int k = 0; k < 4; ++k) {
        h[k] = __float2bfloat16(f[k]);
        l[k] = __float2bfloat16(f[k] - __bfloat162float(h[k]));
    }
    __nv_bfloat16* hp = which == 0 ? g_Ahi : (which == 1 ? g_Whi : g_OWhi);
    __nv_bfloat16* lp = which == 0 ? g_Alo : (which == 1 ? g_Wlo : g_OWlo);
    *(uint2*)&hp[i * 4] = *(uint2*)h;
    *(uint2*)&lp[i * 4] = *(uint2*)l;
}

// ---------------------------------------------------------------------------
// Split-bf16 mma.sync GEMM, cp.async double-buffered, 2 CTAs/SM.
// (unchanged from R6)
// ---------------------------------------------------------------------------
#define SPAD 40
#define ARR_B 10240
#define STG_B (4 * ARR_B)
#define GEMM_SMEM (2 * STG_B)

template <int MODE>
__global__ __launch_bounds__(256, 2) void mma_gemm(
    const float* __restrict__ bias, float* __restrict__ outp)
{
    extern __shared__ __align__(16) char gsm[];
    const uint32_t u0 = s2u(gsm);

    const __nv_bfloat16* Ah = (MODE == 0) ? g_Ahi : g_Xhi;
    const __nv_bfloat16* Al = (MODE == 0) ? g_Alo : g_Xlo;
    const __nv_bfloat16* Bh = (MODE == 0) ? g_Whi : g_OWhi;
    const __nv_bfloat16* Bl = (MODE == 0) ? g_Wlo : g_OWlo;

    const int m0 = blockIdx.y << 7;
    const int n0 = blockIdx.x << 7;
    const int tid = threadIdx.x;
    const int wid = tid >> 5, lane = tid & 31;
    const int wm = wid >> 2, wn = wid & 3;
    const int grp = lane >> 2, tig = lane & 3;

    const int lrow0 = tid >> 2,        lc40 = tid & 3;
    const int lrow1 = (tid + 256) >> 2, lc41 = (tid + 256) & 3;
    const uint32_t sb0 = (uint32_t)(lrow0 * SPAD + lc40 * 8) * 2;
    const uint32_t sb1 = (uint32_t)(lrow1 * SPAD + lc41 * 8) * 2;

    const uint32_t aBase = (uint32_t)(((wm * 64) + (lane & 15)) * SPAD +
                                      (lane >> 4) * 8) * 2;
    const uint32_t bBase = (uint32_t)(((wn * 32) + (lane & 7)) * SPAD +
                                      ((lane >> 3) & 1) * 8) * 2;

    float acc[4][4][4] = {};

    auto issue = [&](int stage, int kc) {
        const int ko = kc * 4;
        const size_t ga0 = (size_t)(m0 + lrow0) * 128 + ko + lc40;
        const size_t ga1 = (size_t)(m0 + lrow1) * 128 + ko + lc41;
        const size_t gb0 = (size_t)(n0 + lrow0) * 128 + ko + lc40;
        const size_t gb1 = (size_t)(n0 + lrow1) * 128 + ko + lc41;
        const uint32_t s = u0 + (uint32_t)stage * STG_B;
        cpa16(s + sb0,             (const uint4*)Ah + ga0);
        cpa16(s + sb1,             (const uint4*)Ah + ga1);
        cpa16(s + ARR_B + sb0,     (const uint4*)Al + ga0);
        cpa16(s + ARR_B + sb1,     (const uint4*)Al + ga1);
        cpa16(s + 2 * ARR_B + sb0, (const uint4*)Bh + gb0);
        cpa16(s + 2 * ARR_B + sb1, (const uint4*)Bh + gb1);
        cpa16(s + 3 * ARR_B + sb0, (const uint4*)Bl + gb0);
        cpa16(s + 3 * ARR_B + sb1, (const uint4*)Bl + gb1);
        cpa_commit();
    };

    issue(0, 0);
    issue(1, 1);

    for (int kc = 0; kc < 32; ++kc) {
        cpa_wait<1>();
        __syncthreads();

        const uint32_t uAh = u0 + (uint32_t)(kc & 1) * STG_B;
        const uint32_t uAl = uAh + ARR_B;
        const uint32_t uBh = uAl + ARR_B;
        const uint32_t uBl = uBh + ARR_B;

        #pragma unroll
        for (int ks = 0; ks < 2; ++ks) {
            const uint32_t kb = (uint32_t)(ks * 16) * 2;
            uint32_t fbh[4][2], fbl[4][2];
            #pragma unroll
            for (int ni = 0; ni < 4; ++ni) {
                uint32_t off = bBase + kb + (uint32_t)(ni * 8 * SPAD) * 2;
                asm volatile("ldmatrix.sync.aligned.m8n8.x2.shared.b16 {%0,%1}, [%2];"
                    : "=r"(fbh[ni][0]), "=r"(fbh[ni][1]) : "r"(uBh + off));
                asm volatile("ldmatrix.sync.aligned.m8n8.x2.shared.b16 {%0,%1}, [%2];"
                    : "=r"(fbl[ni][0]), "=r"(fbl[ni][1]) : "r"(uBl + off));
            }
            #pragma unroll
            for (int mi = 0; mi < 4; ++mi) {
                uint32_t fah[4], fal[4];
                uint32_t off = aBase + kb + (uint32_t)(mi * 16 * SPAD) * 2;
                ldsm_x4(fah, uAh + off);
                ldsm_x4(fal, uAl + off);
                #pragma unroll
                for (int ni = 0; ni < 4; ++ni) {
                    mma16816(acc[mi][ni], fah, fbh[ni]);
                    mma16816(acc[mi][ni], fah, fbl[ni]);
                    mma16816(acc[mi][ni], fal, fbh[ni]);
                }
            }
        }
        __syncthreads();
        if (kc + 2 < 32) issue(kc & 1, kc + 2);
    }

    #pragma unroll
    for (int mi = 0; mi < 4; ++mi) {
        #pragma unroll
        for (int ni = 0; ni < 4; ++ni) {
            const int col = n0 + wn * 32 + ni * 8 + tig * 2;
            const float bv0 = bias[col], bv1 = bias[col + 1];
            #pragma unroll
            for (int rh = 0; rh < 2; ++rh) {
                const int row = m0 + wm * 64 + mi * 16 + grp + rh * 8;
                float v0 = acc[mi][ni][rh * 2 + 0] + bv0;
                float v1 = acc[mi][ni][rh * 2 + 1] + bv1;
                if (MODE == 0) {
                    const int part = col >> 10;
                    const int h = (col & 1023) >> 6;
                    const int d = col & 63;
                    const int b = row >> 10, l = row & 1023;
                    size_t idx = ((size_t)((b << 4) + h) * 1024 + l) * 64 + d;
                    if (part == 0) {
                        v0 *= 0.125f; v1 *= 0.125f;
                        float2 o = {v0, v1};
                        *(float2*)&g_Q[idx] = o;
                        split2(g_Qhi, g_Qlo, idx, v0, v1);
                    } else if (part == 1) {
                        split2(g_Khi, g_Klo, idx, v0, v1);
                    } else {
                        split2(g_Vhi, g_Vlo, idx, v0, v1);
                    }
                } else {
                    float2 o = {v0, v1};
                    *(float2*)&outp[row * 1024 + col] = o;
                }
            }
        }
    }
}

// ---------------------------------------------------------------------------
// Stage 2: bias_r[row, r] = g_Q[row,:] . rel_pe[r,:]
// ---------------------------------------------------------------------------
__global__ __launch_bounds__(256) void bias_gemm(const float* __restrict__ pe)
{
    __shared__ float pes[129 * 64];
    __shared__ float qs[32 * 64];
    const int tid = threadIdx.x;
    const int row0 = blockIdx.x << 5;
    for (int i = tid; i < 129 * 64; i += 256) pes[i] = pe[i];
    for (int i = tid; i < 32 * 64; i += 256) qs[i] = g_Q[row0 * 64 + i];
    __syncthreads();
    for (int idx = tid; idx < 32 * 129; idx += 256) {
        int r = idx / 129, c = idx - r * 129;
        float s = 0.f;
        #pragma unroll
        for (int d = 0; d < 64; d += 4) {
            float4 a = *(const float4*)&qs[(r << 6) + d];
            float4 p = *(const float4*)&pes[(c << 6) + d];
            s = fmaf(a.x, p.x, s); s = fmaf(a.y, p.y, s);
            s = fmaf(a.z, p.z, s); s = fmaf(a.w, p.w, s);
        }
        g_bias[(row0 + r) * BSTR + c] = s;
    }
}

// ---------------------------------------------------------------------------
// Stage 3: flash attention, mma.sync split-bf16, j-tile 64, 2 CTAs/SM.
// smem: K hi/lo + V hi/lo (64x72 each, 36864 B) + bias 128x130 fp32 (66560 B)
//     = 103424 B -> 2 CTAs/SM. K(t+1) issued after S(t); V(t+1) after PV(t).
// ---------------------------------------------------------------------------
#define AT_SPAD 72
#define AT_ARR_B (64 * AT_SPAD * 2)       // 9216
#define AT_KV_B  (4 * AT_ARR_B)           // 36864
#define ATTN_SMEM (AT_KV_B + 128 * 130 * 4)
#define NJT 16

__global__ __launch_bounds__(256, 2) void attn_mma()
{
    extern __shared__ __align__(16) char smem_raw[];
    const uint32_t uKh = s2u(smem_raw);
    const uint32_t uKl = uKh + AT_ARR_B;
    const uint32_t uVh = uKl + AT_ARR_B;
    const uint32_t uVl = uVh + AT_ARR_B;
    float* sB = (float*)(smem_raw + AT_KV_B);
    const uint32_t uB = s2u(sB);

    const int bh = blockIdx.y;
    const int i0 = blockIdx.x << 7;
    const int tid = threadIdx.x;
    const int w = tid >> 5, lane = tid & 31;
    const int grp = lane >> 2, tig = lane & 3;

    const uint4* gKh = (const uint4*)(g_Khi + (size_t)bh * 65536);
    const uint4* gKl = (const uint4*)(g_Klo + (size_t)bh * 65536);
    const uint4* gVh = (const uint4*)(g_Vhi + (size_t)bh * 65536);
    const uint4* gVl = (const uint4*)(g_Vlo + (size_t)bh * 65536);

    // cp.async issue of one 64-row K or V tile (hi+lo): each thread copies
    // uint4 columns cc and cc+1 of its row (4 threads x 2 = 8 uint4 per row)
    const int cr = tid >> 2;             // 0..63 row
    const int cc = (tid & 3) * 2;        // uint4 col {0,2,4,6}
    const uint32_t cdst = (uint32_t)(cr * AT_SPAD * 2) + (uint32_t)cc * 16;
    auto issue_k = [&](int jt) {
        const uint4* h = gKh + jt * 512 + cr * 8 + cc;
        const uint4* l = gKl + jt * 512 + cr * 8 + cc;
        cpa16(uKh + cdst, h);      cpa16(uKh + cdst + 16, h + 1);
        cpa16(uKl + cdst, l);      cpa16(uKl + cdst + 16, l + 1);
        cpa_commit();
    };
    auto issue_v = [&](int jt) {
        const uint4* h = gVh + jt * 512 + cr * 8 + cc;
        const uint4* l = gVl + jt * 512 + cr * 8 + cc;
        cpa16(uVh + cdst, h);      cpa16(uVh + cdst + 16, h + 1);
        cpa16(uVl + cdst, l);      cpa16(uVl + cdst + 16, l + 1);
        cpa_commit();
    };

    issue_k(0);
    issue_v(0);

    // stage Q (hi/lo) through the bias smem area, grab A-fragments
    const size_t qbase = (size_t)bh * 65536 + (size_t)i0 * 64;
    {
        const uint4* srcH = (const uint4*)(g_Qhi + qbase);
        const uint4* srcL = (const uint4*)(g_Qlo + qbase);
        __nv_bfloat16* t0 = (__nv_bfloat16*)sB;
        __nv_bfloat16* t1 = t0 + 128 * AT_SPAD;
        #pragma unroll
        for (int k = 0; k < 4; ++k) {
            int u = tid + k * 256;
            int r = u >> 3, c = (u & 7) * 8;
            *(uint4*)&t0[r * AT_SPAD + c] = srcH[u];
            *(uint4*)&t1[r * AT_SPAD + c] = srcL[u];
        }
    }
    __syncthreads();

    uint32_t qh[4][4], ql[4][4];
    {
        uint32_t ro = (uint32_t)((w * 16 + (lane & 15)) * AT_SPAD +
                                 (lane >> 4) * 8) * 2;
        #pragma unroll
        for (int ks = 0; ks < 4; ++ks) {
            ldsm_x4(qh[ks], uB + ro + ks * 32);
            ldsm_x4(ql[ks], uB + (uint32_t)(128 * AT_SPAD * 2) + ro + ks * 32);
        }
    }
    __syncthreads();

    // fill bias tile (overlaps with in-flight K0/V0 cp.async)
    for (int idx = tid; idx < 128 * 129; idx += 256) {
        int r = idx / 129, c = idx - r * 129;
        sB[r * 130 + c] = g_bias[(size_t)(bh * 1024 + i0 + r) * BSTR + c];
    }

    float mr[2] = {-1e30f, -1e30f};
    float lr[2] = {0.f, 0.f};
    float o[8][4] = {};

    const int r0loc = w * 16 + grp;
    const float* brow0 = &sB[r0loc * 130 + 64];
    const float* brow1 = &sB[(r0loc + 8) * 130 + 64];

    for (int jt = 0; jt < NJT; ++jt) {
        // wait for K_jt (leave newer V_jt possibly in flight)
        cpa_wait<1>();
        __syncthreads();

        // ---- S = Q K^T (3 terms), 64 cols ----
        float s[8][4];
        #pragma unroll
        for (int jb = 0; jb < 8; ++jb)
            #pragma unroll
            for (int e = 0; e < 4; ++e) s[jb][e] = 0.f;

        #pragma unroll
        for (int ks = 0; ks < 4; ++ks) {
            #pragma unroll
            for (int jp = 0; jp < 4; ++jp) {
                uint32_t kfh[4], kfl[4];
                uint32_t off = (uint32_t)((jp * 16 + (lane & 7) +
                                           ((lane >> 4) << 3)) * AT_SPAD +
                                          ks * 16 + ((lane >> 3) & 1) * 8) * 2;
                ldsm_x4(kfh, uKh + off);
                ldsm_x4(kfl, uKl + off);
                mma16816(s[2 * jp],     qh[ks], kfh);
                mma16816(s[2 * jp],     qh[ks], kfl);
                mma16816(s[2 * jp],     ql[ks], kfh);
                mma16816(s[2 * jp + 1], qh[ks], kfh + 2);
                mma16816(s[2 * jp + 1], qh[ks], kfl + 2);
                mma16816(s[2 * jp + 1], ql[ks], kfh + 2);
            }
        }
        __syncthreads();                     // all warps done reading K smem
        if (jt + 1 < NJT) issue_k(jt + 1);   // K(t+1) overlaps softmax + PV

        // ---- relative-PE bias ----
        const int jbase = (jt << 6) + tig * 2 - (i0 + r0loc);
        #pragma unroll
        for (int jb = 0; jb < 8; ++jb) {
            int d0 = jbase + jb * 8;
            int dA = min(max(d0,     -64), 64);
            int dB = min(max(d0 + 1, -64), 64);
            int dC = min(max(d0 - 8, -64), 64);
            int dD = min(max(d0 - 7, -64), 64);
            s[jb][0] += brow0[dA];
            s[jb][1] += brow0[dB];
            s[jb][2] += brow1[dC];
            s[jb][3] += brow1[dD];
        }

        // ---- online softmax ----
        float mx0 = -1e30f, mx1 = -1e30f;
        #pragma unroll
        for (int jb = 0; jb < 8; ++jb) {
            mx0 = fmaxf(mx0, fmaxf(s[jb][0], s[jb][1]));
            mx1 = fmaxf(mx1, fmaxf(s[jb][2], s[jb][3]));
        }
        mx0 = fmaxf(mx0, __shfl_xor_sync(0xffffffffu, mx0, 1));
        mx0 = fmaxf(mx0, __shfl_xor_sync(0xffffffffu, mx0, 2));
        mx1 = fmaxf(mx1, __shfl_xor_sync(0xffffffffu, mx1, 1));
        mx1 = fmaxf(mx1, __shfl_xor_sync(0xffffffffu, mx1, 2));
        float nm0 = fmaxf(mr[0], mx0), nm1 = fmaxf(mr[1], mx1);
        float sc0 = __expf(mr[0] - nm0), sc1 = __expf(mr[1] - nm1);
        float ps0 = 0.f, ps1 = 0.f;
        #pragma unroll
        for (int jb = 0; jb < 8; ++jb) {
            s[jb][0] = __expf(s[jb][0] - nm0);
            s[jb][1] = __expf(s[jb][1] - nm0);
            s[jb][2] = __expf(s[jb][2] - nm1);
            s[jb][3] = __expf(s[jb][3] - nm1);
            ps0 += s[jb][0] + s[jb][1];
            ps1 += s[jb][2] + s[jb][3];
        }
        ps0 += __shfl_xor_sync(0xffffffffu, ps0, 1);
        ps0 += __shfl_xor_sync(0xffffffffu, ps0, 2);
        ps1 += __shfl_xor_sync(0xffffffffu, ps1, 1);
        ps1 += __shfl_xor_sync(0xffffffffu, ps1, 2);
        lr[0] = lr[0] * sc0 + ps0; mr[0] = nm0;
        lr[1] = lr[1] * sc1 + ps1; mr[1] = nm1;
        #pragma unroll
        for (int nd = 0; nd < 8; ++nd) {
            o[nd][0] *= sc0; o[nd][1] *= sc0;
            o[nd][2] *= sc1; o[nd][3] *= sc1;
        }

        // wait for V_jt (leave newer K_{jt+1} in flight)
        if (jt + 1 < NJT) cpa_wait<1>(); else cpa_wait<0>();
        __syncthreads();

        // ---- O += P V (3 terms) ----
        #pragma unroll
        for (int kk = 0; kk < 4; ++kk) {
            uint32_t ah[4], al[4];
            pack_hl(s[2 * kk][0],     s[2 * kk][1],     ah[0], al[0]);
            pack_hl(s[2 * kk][2],     s[2 * kk][3],     ah[1], al[1]);
            pack_hl(s[2 * kk + 1][0], s[2 * kk + 1][1], ah[2], al[2]);
            pack_hl(s[2 * kk + 1][2], s[2 * kk + 1][3], ah[3], al[3]);
            #pragma unroll
            for (int np = 0; np < 4; ++np) {
                uint32_t vfh[4], vfl[4];
                uint32_t off = (uint32_t)((kk * 16 + (lane & 7) +
                                           ((lane >> 3) & 1) * 8) * AT_SPAD +
                                          np * 16 + (lane >> 4) * 8) * 2;
                ldsm_x4_t(vfh, uVh + off);
                ldsm_x4_t(vfl, uVl + off);
                mma16816(o[2 * np],     ah, vfh);
                mma16816(o[2 * np],     ah, vfl);
                mma16816(o[2 * np],     al, vfh);
                mma16816(o[2 * np + 1], ah, vfh + 2);
                mma16816(o[2 * np + 1], ah, vfl + 2);
                mma16816(o[2 * np + 1], al, vfh + 2);
            }
        }
        if (jt + 1 < NJT) {
            __syncthreads();                 // all warps done reading V smem
            issue_v(jt + 1);                 // V(t+1) overlaps next S
        }
    }

    // ---- finalize + write X hi/lo in (b,l,e) layout ----
    const float inv0 = 1.0f / lr[0], inv1 = 1.0f / lr[1];
    const int b = bh >> 4, h = bh & 15;
    const size_t row0 = (size_t)(b * 1024 + i0 + r0loc);
    const size_t row1 = row0 + 8;
    #pragma unroll
    for (int nd = 0; nd < 8; ++nd) {
        const int col = h * 64 + nd * 8 + tig * 2;
        uint32_t hi, lo;
        pack_hl(o[nd][0] * inv0, o[nd][1] * inv0, hi, lo);
        *(uint32_t*)&g_Xhi[row0 * 1024 + col] = hi;
        *(uint32_t*)&g_Xlo[row0 * 1024 + col] = lo;
        pack_hl(o[nd][2] * inv1, o[nd][3] * inv1, hi, lo);
        *(uint32_t*)&g_Xhi[row1 * 1024 + col] = hi;
        *(uint32_t*)&g_Xlo[row1 * 1024 + col] = lo;
    }
}

// ---------------------------------------------------------------------------
extern "C" void kernel_launch(void* const* d_in, const int* in_sizes, int n_in,
                              void* d_out, int out_size)
{
    const float* q  = (const float*)d_in[0];
    const float* w3 = (const float*)d_in[1];
    const float* b3 = (const float*)d_in[2];
    const float* ow = (const float*)d_in[3];
    const float* ob = (const float*)d_in[4];
    const float* pe = (const float*)d_in[5];
    float* out = (float*)d_out;

    cudaFuncSetAttribute(attn_mma, cudaFuncAttributeMaxDynamicSharedMemorySize,
                         ATTN_SMEM);
    cudaFuncSetAttribute(mma_gemm<0>, cudaFuncAttributeMaxDynamicSharedMemorySize,
                         GEMM_SMEM);
    cudaFuncSetAttribute(mma_gemm<1>, cudaFuncAttributeMaxDynamicSharedMemorySize,
                         GEMM_SMEM);

    split_kernel<<<4096, 256>>>(q,  4096 * 1024 / 4, 0);
    split_kernel<<<3072, 256>>>(w3, 3072 * 1024 / 4, 1);
    split_kernel<<<1024, 256>>>(ow, 1024 * 1024 / 4, 2);

    mma_gemm<0><<<dim3(24, 32), 256, GEMM_SMEM>>>(b3, nullptr);
    bias_gemm<<<2048, 256>>>(pe);
    attn_mma<<<dim3(8, 64), 256, ATTN_SMEM>>>();
    mma_gemm<1><<<dim3(8, 32), 256, GEMM_SMEM>>>(ob, out);
}

// round 9
// speedup vs baseline: 2.0453x; 1.0100x over previous
#include <cuda_runtime.h>
#include <cuda_bf16.h>
#include <cstdint>

// ---------------------------------------------------------------------------
// RelativeSelfAttention: B=4, L=1024, E=1024, H=16, D=64, K=64 (129 PE rows)
// R9: attention with no smem bias tile (band-constant + L2 gather),
//     Q resident in smem, double-buffered K/V, true 2 CTAs/SM.
// ---------------------------------------------------------------------------

#define NBH   64
#define BSTR  132

__device__ float g_Q[NBH * 1024 * 64];          // scaled fp32 Q (for bias_gemm)
__device__ float g_bias[NBH * 1024 * BSTR];

__device__ __nv_bfloat16 g_Ahi[4096 * 1024], g_Alo[4096 * 1024];
__device__ __nv_bfloat16 g_Whi[3072 * 1024], g_Wlo[3072 * 1024];
__device__ __nv_bfloat16 g_OWhi[1024 * 1024], g_OWlo[1024 * 1024];
__device__ __nv_bfloat16 g_Xhi[4096 * 1024], g_Xlo[4096 * 1024];
__device__ __nv_bfloat16 g_Qhi[NBH * 65536], g_Qlo[NBH * 65536];
__device__ __nv_bfloat16 g_Khi[NBH * 65536], g_Klo[NBH * 65536];
__device__ __nv_bfloat16 g_Vhi[NBH * 65536], g_Vlo[NBH * 65536];

// ------------------------------- PTX helpers -------------------------------
__device__ __forceinline__ uint32_t s2u(const void* p) {
    return (uint32_t)__cvta_generic_to_shared(p);
}
__device__ __forceinline__ void ldsm_x4(uint32_t* r, uint32_t addr) {
    asm volatile("ldmatrix.sync.aligned.m8n8.x4.shared.b16 {%0,%1,%2,%3}, [%4];"
        : "=r"(r[0]), "=r"(r[1]), "=r"(r[2]), "=r"(r[3]) : "r"(addr));
}
__device__ __forceinline__ void ldsm_x4_t(uint32_t* r, uint32_t addr) {
    asm volatile("ldmatrix.sync.aligned.m8n8.x4.trans.shared.b16 {%0,%1,%2,%3}, [%4];"
        : "=r"(r[0]), "=r"(r[1]), "=r"(r[2]), "=r"(r[3]) : "r"(addr));
}
__device__ __forceinline__ void mma16816(float* c, const uint32_t* a,
                                         const uint32_t* b) {
    asm volatile(
        "mma.sync.aligned.m16n8k16.row.col.f32.bf16.bf16.f32 "
        "{%0,%1,%2,%3}, {%4,%5,%6,%7}, {%8,%9}, {%0,%1,%2,%3};"
        : "+f"(c[0]), "+f"(c[1]), "+f"(c[2]), "+f"(c[3])
        : "r"(a[0]), "r"(a[1]), "r"(a[2]), "r"(a[3]), "r"(b[0]), "r"(b[1]));
}
__device__ __forceinline__ void cpa16(uint32_t dst, const void* src) {
    asm volatile("cp.async.cg.shared.global [%0], [%1], 16;"
                 :: "r"(dst), "l"(src) : "memory");
}
__device__ __forceinline__ void cpa_commit() {
    asm volatile("cp.async.commit_group;" ::: "memory");
}
template <int N>
__device__ __forceinline__ void cpa_wait() {
    asm volatile("cp.async.wait_group %0;" :: "n"(N) : "memory");
}
__device__ __forceinline__ void pack_hl(float v0, float v1,
                                        uint32_t& hi, uint32_t& lo) {
    __nv_bfloat16 h0 = __float2bfloat16(v0), h1 = __float2bfloat16(v1);
    float l0 = v0 - __bfloat162float(h0), l1 = v1 - __bfloat162float(h1);
    __nv_bfloat162 H; H.x = h0; H.y = h1;
    __nv_bfloat162 L; L.x = __float2bfloat16(l0); L.y = __float2bfloat16(l1);
    hi = *(uint32_t*)&H; lo = *(uint32_t*)&L;
}
__device__ __forceinline__ void split2(__nv_bfloat16* hp, __nv_bfloat16* lp,
                                       size_t idx, float v0, float v1) {
    uint32_t hi, lo;
    pack_hl(v0, v1, hi, lo);
    *(uint32_t*)&hp[idx] = hi;
    *(uint32_t*)&lp[idx] = lo;
}

// ---------------------------------------------------------------------------
// fp32 -> bf16 hi/lo split (which: 0=A(q), 1=W3, 2=out_w)
// ---------------------------------------------------------------------------
__global__ __launch_bounds__(256) void split_kernel(
    const float* __restrict__ src, int n4, int which)
{
    int i = blockIdx.x * 256 + threadIdx.x;
    if (i >= n4) return;
    float4 v = ((const float4*)src)[i];
    __nv_bfloat16 h[4], l[4];
    float f[4] = {v.x, v.y, v.z, v.w};
    #pragma unroll
    for (int k = 0; k < 4; ++k) {
        h[k] = __float2bfloat16(f[k]);
        l[k] = __float2bfloat16(f[k] - __bfloat162float(h[k]));
    }
    __nv_bfloat16* hp = which == 0 ? g_Ahi : (which == 1 ? g_Whi : g_OWhi);
    __nv_bfloat16* lp = which == 0 ? g_Alo : (which == 1 ? g_Wlo : g_OWlo);
    *(uint2*)&hp[i * 4] = *(uint2*)h;
    *(uint2*)&lp[i * 4] = *(uint2*)l;
}

// ---------------------------------------------------------------------------
// Split-bf16 mma.sync GEMM, cp.async double-buffered, 2 CTAs/SM.
// (unchanged from R6/R8 — at the mma.sync roofline)
// ---------------------------------------------------------------------------
#define SPAD 40
#define ARR_B 10240
#define STG_B (4 * ARR_B)
#define GEMM_SMEM (2 * STG_B)

template <int MODE>
__global__ __launch_bounds__(256, 2) void mma_gemm(
    const float* __restrict__ bias, float* __restrict__ outp)
{
    extern __shared__ __align__(16) char gsm[];
    const uint32_t u0 = s2u(gsm);

    const __nv_bfloat16* Ah = (MODE == 0) ? g_Ahi : g_Xhi;
    const __nv_bfloat16* Al = (MODE == 0) ? g_Alo : g_Xlo;
    const __nv_bfloat16* Bh = (MODE == 0) ? g_Whi : g_OWhi;
    const __nv_bfloat16* Bl = (MODE == 0) ? g_Wlo : g_OWlo;

    const int m0 = blockIdx.y << 7;
    const int n0 = blockIdx.x << 7;
    const int tid = threadIdx.x;
    const int wid = tid >> 5, lane = tid & 31;
    const int wm = wid >> 2, wn = wid & 3;
    const int grp = lane >> 2, tig = lane & 3;

    const int lrow0 = tid >> 2,        lc40 = tid & 3;
    const int lrow1 = (tid + 256) >> 2, lc41 = (tid + 256) & 3;
    const uint32_t sb0 = (uint32_t)(lrow0 * SPAD + lc40 * 8) * 2;
    const uint32_t sb1 = (uint32_t)(lrow1 * SPAD + lc41 * 8) * 2;

    const uint32_t aBase = (uint32_t)(((wm * 64) + (lane & 15)) * SPAD +
                                      (lane >> 4) * 8) * 2;
    const uint32_t bBase = (uint32_t)(((wn * 32) + (lane & 7)) * SPAD +
                                      ((lane >> 3) & 1) * 8) * 2;

    float acc[4][4][4] = {};

    auto issue = [&](int stage, int kc) {
        const int ko = kc * 4;
        const size_t ga0 = (size_t)(m0 + lrow0) * 128 + ko + lc40;
        const size_t ga1 = (size_t)(m0 + lrow1) * 128 + ko + lc41;
        const size_t gb0 = (size_t)(n0 + lrow0) * 128 + ko + lc40;
        const size_t gb1 = (size_t)(n0 + lrow1) * 128 + ko + lc41;
        const uint32_t s = u0 + (uint32_t)stage * STG_B;
        cpa16(s + sb0,             (const uint4*)Ah + ga0);
        cpa16(s + sb1,             (const uint4*)Ah + ga1);
        cpa16(s + ARR_B + sb0,     (const uint4*)Al + ga0);
        cpa16(s + ARR_B + sb1,     (const uint4*)Al + ga1);
        cpa16(s + 2 * ARR_B + sb0, (const uint4*)Bh + gb0);
        cpa16(s + 2 * ARR_B + sb1, (const uint4*)Bh + gb1);
        cpa16(s + 3 * ARR_B + sb0, (const uint4*)Bl + gb0);
        cpa16(s + 3 * ARR_B + sb1, (const uint4*)Bl + gb1);
        cpa_commit();
    };

    issue(0, 0);
    issue(1, 1);

    for (int kc = 0; kc < 32; ++kc) {
        cpa_wait<1>();
        __syncthreads();

        const uint32_t uAh = u0 + (uint32_t)(kc & 1) * STG_B;
        const uint32_t uAl = uAh + ARR_B;
        const uint32_t uBh = uAl + ARR_B;
        const uint32_t uBl = uBh + ARR_B;

        #pragma unroll
        for (int ks = 0; ks < 2; ++ks) {
            const uint32_t kb = (uint32_t)(ks * 16) * 2;
            uint32_t fbh[4][2], fbl[4][2];
            #pragma unroll
            for (int ni = 0; ni < 4; ++ni) {
                uint32_t off = bBase + kb + (uint32_t)(ni * 8 * SPAD) * 2;
                asm volatile("ldmatrix.sync.aligned.m8n8.x2.shared.b16 {%0,%1}, [%2];"
                    : "=r"(fbh[ni][0]), "=r"(fbh[ni][1]) : "r"(uBh + off));
                asm volatile("ldmatrix.sync.aligned.m8n8.x2.shared.b16 {%0,%1}, [%2];"
                    : "=r"(fbl[ni][0]), "=r"(fbl[ni][1]) : "r"(uBl + off));
            }
            #pragma unroll
            for (int mi = 0; mi < 4; ++mi) {
                uint32_t fah[4], fal[4];
                uint32_t off = aBase + kb + (uint32_t)(mi * 16 * SPAD) * 2;
                ldsm_x4(fah, uAh + off);
                ldsm_x4(fal, uAl + off);
                #pragma unroll
                for (int ni = 0; ni < 4; ++ni) {
                    mma16816(acc[mi][ni], fah, fbh[ni]);
                    mma16816(acc[mi][ni], fah, fbl[ni]);
                    mma16816(acc[mi][ni], fal, fbh[ni]);
                }
            }
        }
        __syncthreads();
        if (kc + 2 < 32) issue(kc & 1, kc + 2);
    }

    #pragma unroll
    for (int mi = 0; mi < 4; ++mi) {
        #pragma unroll
        for (int ni = 0; ni < 4; ++ni) {
            const int col = n0 + wn * 32 + ni * 8 + tig * 2;
            const float bv0 = bias[col], bv1 = bias[col + 1];
            #pragma unroll
            for (int rh = 0; rh < 2; ++rh) {
                const int row = m0 + wm * 64 + mi * 16 + grp + rh * 8;
                float v0 = acc[mi][ni][rh * 2 + 0] + bv0;
                float v1 = acc[mi][ni][rh * 2 + 1] + bv1;
                if (MODE == 0) {
                    const int part = col >> 10;
                    const int h = (col & 1023) >> 6;
                    const int d = col & 63;
                    const int b = row >> 10, l = row & 1023;
                    size_t idx = ((size_t)((b << 4) + h) * 1024 + l) * 64 + d;
                    if (part == 0) {
                        v0 *= 0.125f; v1 *= 0.125f;
                        float2 o = {v0, v1};
                        *(float2*)&g_Q[idx] = o;
                        split2(g_Qhi, g_Qlo, idx, v0, v1);
                    } else if (part == 1) {
                        split2(g_Khi, g_Klo, idx, v0, v1);
                    } else {
                        split2(g_Vhi, g_Vlo, idx, v0, v1);
                    }
                } else {
                    float2 o = {v0, v1};
                    *(float2*)&outp[row * 1024 + col] = o;
                }
            }
        }
    }
}

// ---------------------------------------------------------------------------
// Stage 2: bias_r[row, r] = g_Q[row,:] . rel_pe[r,:]
// ---------------------------------------------------------------------------
__global__ __launch_bounds__(256) void bias_gemm(const float* __restrict__ pe)
{
    __shared__ float pes[129 * 64];
    __shared__ float qs[32 * 64];
    const int tid = threadIdx.x;
    const int row0 = blockIdx.x << 5;
    for (int i = tid; i < 129 * 64; i += 256) pes[i] = pe[i];
    for (int i = tid; i < 32 * 64; i += 256) qs[i] = g_Q[row0 * 64 + i];
    __syncthreads();
    for (int idx = tid; idx < 32 * 129; idx += 256) {
        int r = idx / 129, c = idx - r * 129;
        float s = 0.f;
        #pragma unroll
        for (int d = 0; d < 64; d += 4) {
            float4 a = *(const float4*)&qs[(r << 6) + d];
            float4 p = *(const float4*)&pes[(c << 6) + d];
            s = fmaf(a.x, p.x, s); s = fmaf(a.y, p.y, s);
            s = fmaf(a.z, p.z, s); s = fmaf(a.w, p.w, s);
        }
        g_bias[(row0 + r) * BSTR + c] = s;
    }
}

// ---------------------------------------------------------------------------
// Stage 3: flash attention, mma.sync split-bf16.
// No smem bias tile: out-of-band j uses per-row constants (bias col 0 / 128);
// in-band tiles gather from g_bias via L2 (__ldg).
// smem: 2-stage K/V (2 x 36864) + Q hi/lo resident (36864) = 110592 B
//   -> 2 CTAs/SM with <=128 regs.
// ---------------------------------------------------------------------------
#define AT_SPAD 72
#define AT_ARR_B (64 * AT_SPAD * 2)       // 9216 per 64-row array
#define AT_STG_B (4 * AT_ARR_B)           // 36864 per stage (Kh,Kl,Vh,Vl)
#define AT_Q_B   (128 * AT_SPAD * 2)      // 18432 per Q array
#define ATTN_SMEM (2 * AT_STG_B + 2 * AT_Q_B)
#define NJT 16

__global__ __launch_bounds__(256, 2) void attn_mma()
{
    extern __shared__ __align__(16) char smem_raw[];
    const uint32_t u0 = s2u(smem_raw);
    const uint32_t uQh = u0 + 2 * AT_STG_B;
    const uint32_t uQl = uQh + AT_Q_B;

    const int bh = blockIdx.y;
    const int i0 = blockIdx.x << 7;
    const int tid = threadIdx.x;
    const int w = tid >> 5, lane = tid & 31;
    const int grp = lane >> 2, tig = lane & 3;

    const uint4* gKh = (const uint4*)(g_Khi + (size_t)bh * 65536);
    const uint4* gKl = (const uint4*)(g_Klo + (size_t)bh * 65536);
    const uint4* gVh = (const uint4*)(g_Vhi + (size_t)bh * 65536);
    const uint4* gVl = (const uint4*)(g_Vlo + (size_t)bh * 65536);

    // K/V tile loader: each thread copies uint4 cols cc, cc+1 of its row
    const int cr = tid >> 2;
    const int cc = (tid & 3) * 2;
    const uint32_t cdst = (uint32_t)(cr * AT_SPAD * 2) + (uint32_t)cc * 16;
    auto issue_kv = [&](int jt) {
        const uint32_t s = u0 + (uint32_t)(jt & 1) * AT_STG_B;
        const uint4* kh = gKh + jt * 512 + cr * 8 + cc;
        const uint4* kl = gKl + jt * 512 + cr * 8 + cc;
        const uint4* vh = gVh + jt * 512 + cr * 8 + cc;
        const uint4* vl = gVl + jt * 512 + cr * 8 + cc;
        cpa16(s + cdst, kh);                    cpa16(s + cdst + 16, kh + 1);
        cpa16(s + AT_ARR_B + cdst, kl);         cpa16(s + AT_ARR_B + cdst + 16, kl + 1);
        cpa16(s + 2 * AT_ARR_B + cdst, vh);     cpa16(s + 2 * AT_ARR_B + cdst + 16, vh + 1);
        cpa16(s + 3 * AT_ARR_B + cdst, vl);     cpa16(s + 3 * AT_ARR_B + cdst + 16, vl + 1);
        cpa_commit();
    };

    issue_kv(0);

    // stage Q hi/lo into resident smem (plain stores; visible after first sync)
    {
        const size_t qbase = (size_t)bh * 65536 + (size_t)i0 * 64;
        const uint4* srcH = (const uint4*)(g_Qhi + qbase);
        const uint4* srcL = (const uint4*)(g_Qlo + qbase);
        __nv_bfloat16* tQh = (__nv_bfloat16*)(smem_raw + 2 * AT_STG_B);
        __nv_bfloat16* tQl = tQh + 128 * AT_SPAD;
        #pragma unroll
        for (int k = 0; k < 4; ++k) {
            int u = tid + k * 256;
            int r = u >> 3, c = (u & 7) * 8;
            *(uint4*)&tQh[r * AT_SPAD + c] = srcH[u];
            *(uint4*)&tQl[r * AT_SPAD + c] = srcL[u];
        }
    }

    // per-row bias pointers + out-of-band constants (cols 0 and 128)
    const int r0g = i0 + w * 16 + grp;        // global i of row 0
    const int r1g = r0g + 8;
    const float* browG0 = g_bias + (size_t)(bh * 1024 + r0g) * BSTR + 64;
    const float* browG1 = g_bias + (size_t)(bh * 1024 + r1g) * BSTR + 64;
    const float clo0 = __ldg(browG0 - 64), chi0 = __ldg(browG0 + 64);
    const float clo1 = __ldg(browG1 - 64), chi1 = __ldg(browG1 + 64);

    float mr[2] = {-1e30f, -1e30f};
    float lr[2] = {0.f, 0.f};
    float o[8][4] = {};

    const uint32_t qro = (uint32_t)((w * 16 + (lane & 15)) * AT_SPAD +
                                    (lane >> 4) * 8) * 2;

    for (int jt = 0; jt < NJT; ++jt) {
        if (jt + 1 < NJT) issue_kv(jt + 1);
        if (jt + 1 < NJT) cpa_wait<1>(); else cpa_wait<0>();
        __syncthreads();

        const uint32_t uKh = u0 + (uint32_t)(jt & 1) * AT_STG_B;
        const uint32_t uKl = uKh + AT_ARR_B;
        const uint32_t uVh = uKl + AT_ARR_B;
        const uint32_t uVl = uVh + AT_ARR_B;
        const int j0 = jt << 6;

        // ---- S = Q K^T (3 terms), Q fragments reloaded from smem ----
        float s[8][4];
        #pragma unroll
        for (int jb = 0; jb < 8; ++jb)
            #pragma unroll
            for (int e = 0; e < 4; ++e) s[jb][e] = 0.f;

        #pragma unroll
        for (int ks = 0; ks < 4; ++ks) {
            uint32_t qh[4], ql[4];
            ldsm_x4(qh, uQh + qro + ks * 32);
            ldsm_x4(ql, uQl + qro + ks * 32);
            #pragma unroll
            for (int jp = 0; jp < 4; ++jp) {
                uint32_t kfh[4], kfl[4];
                uint32_t off = (uint32_t)((jp * 16 + (lane & 7) +
                                           ((lane >> 4) << 3)) * AT_SPAD +
                                          ks * 16 + ((lane >> 3) & 1) * 8) * 2;
                ldsm_x4(kfh, uKh + off);
                ldsm_x4(kfl, uKl + off);
                mma16816(s[2 * jp],     qh, kfh);
                mma16816(s[2 * jp],     qh, kfl);
                mma16816(s[2 * jp],     ql, kfh);
                mma16816(s[2 * jp + 1], qh, kfh + 2);
                mma16816(s[2 * jp + 1], qh, kfl + 2);
                mma16816(s[2 * jp + 1], ql, kfh + 2);
            }
        }

        // ---- relative-PE bias: band-constant or L2 gather ----
        // row 0 (elements [0],[1]; j = j0 + tig*2 + jb*8 + {0,1})
        if (j0 + 63 - r0g <= -64) {
            #pragma unroll
            for (int jb = 0; jb < 8; ++jb) { s[jb][0] += clo0; s[jb][1] += clo0; }
        } else if (j0 - r0g >= 64) {
            #pragma unroll
            for (int jb = 0; jb < 8; ++jb) { s[jb][0] += chi0; s[jb][1] += chi0; }
        } else {
            const int dbase0 = j0 + tig * 2 - r0g;
            #pragma unroll
            for (int jb = 0; jb < 8; ++jb) {
                int dA = min(max(dbase0 + jb * 8,     -64), 64);
                int dB = min(max(dbase0 + jb * 8 + 1, -64), 64);
                s[jb][0] += __ldg(browG0 + dA);
                s[jb][1] += __ldg(browG0 + dB);
            }
        }
        // row 1 (elements [2],[3])
        if (j0 + 63 - r1g <= -64) {
            #pragma unroll
            for (int jb = 0; jb < 8; ++jb) { s[jb][2] += clo1; s[jb][3] += clo1; }
        } else if (j0 - r1g >= 64) {
            #pragma unroll
            for (int jb = 0; jb < 8; ++jb) { s[jb][2] += chi1; s[jb][3] += chi1; }
        } else {
            const int dbase1 = j0 + tig * 2 - r1g;
            #pragma unroll
            for (int jb = 0; jb < 8; ++jb) {
                int dC = min(max(dbase1 + jb * 8,     -64), 64);
                int dD = min(max(dbase1 + jb * 8 + 1, -64), 64);
                s[jb][2] += __ldg(browG1 + dC);
                s[jb][3] += __ldg(browG1 + dD);
            }
        }

        // ---- online softmax ----
        float mx0 = -1e30f, mx1 = -1e30f;
        #pragma unroll
        for (int jb = 0; jb < 8; ++jb) {
            mx0 = fmaxf(mx0, fmaxf(s[jb][0], s[jb][1]));
            mx1 = fmaxf(mx1, fmaxf(s[jb][2], s[jb][3]));
        }
        mx0 = fmaxf(mx0, __shfl_xor_sync(0xffffffffu, mx0, 1));
        mx0 = fmaxf(mx0, __shfl_xor_sync(0xffffffffu, mx0, 2));
        mx1 = fmaxf(mx1, __shfl_xor_sync(0xffffffffu, mx1, 1));
        mx1 = fmaxf(mx1, __shfl_xor_sync(0xffffffffu, mx1, 2));
        float nm0 = fmaxf(mr[0], mx0), nm1 = fmaxf(mr[1], mx1);
        float sc0 = __expf(mr[0] - nm0), sc1 = __expf(mr[1] - nm1);
        float ps0 = 0.f, ps1 = 0.f;
        #pragma unroll
        for (int jb = 0; jb < 8; ++jb) {
            s[jb][0] = __expf(s[jb][0] - nm0);
            s[jb][1] = __expf(s[jb][1] - nm0);
            s[jb][2] = __expf(s[jb][2] - nm1);
            s[jb][3] = __expf(s[jb][3] - nm1);
            ps0 += s[jb][0] + s[jb][1];
            ps1 += s[jb][2] + s[jb][3];
        }
        ps0 += __shfl_xor_sync(0xffffffffu, ps0, 1);
        ps0 += __shfl_xor_sync(0xffffffffu, ps0, 2);
        ps1 += __shfl_xor_sync(0xffffffffu, ps1, 1);
        ps1 += __shfl_xor_sync(0xffffffffu, ps1, 2);
        lr[0] = lr[0] * sc0 + ps0; mr[0] = nm0;
        lr[1] = lr[1] * sc1 + ps1; mr[1] = nm1;
        #pragma unroll
        for (int nd = 0; nd < 8; ++nd) {
            o[nd][0] *= sc0; o[nd][1] *= sc0;
            o[nd][2] *= sc1; o[nd][3] *= sc1;
        }

        // ---- O += P V (3 terms, P packed from registers) ----
        #pragma unroll
        for (int kk = 0; kk < 4; ++kk) {
            uint32_t ah[4], al[4];
            pack_hl(s[2 * kk][0],     s[2 * kk][1],     ah[0], al[0]);
            pack_hl(s[2 * kk][2],     s[2 * kk][3],     ah[1], al[1]);
            pack_hl(s[2 * kk + 1][0], s[2 * kk + 1][1], ah[2], al[2]);
            pack_hl(s[2 * kk + 1][2], s[2 * kk + 1][3], ah[3], al[3]);
            #pragma unroll
            for (int np = 0; np < 4; ++np) {
                uint32_t vfh[4], vfl[4];
                uint32_t off = (uint32_t)((kk * 16 + (lane & 7) +
                                           ((lane >> 3) & 1) * 8) * AT_SPAD +
                                          np * 16 + (lane >> 4) * 8) * 2;
                ldsm_x4_t(vfh, uVh + off);
                ldsm_x4_t(vfl, uVl + off);
                mma16816(o[2 * np],     ah, vfh);
                mma16816(o[2 * np],     ah, vfl);
                mma16816(o[2 * np],     al, vfh);
                mma16816(o[2 * np + 1], ah, vfh + 2);
                mma16816(o[2 * np + 1], ah, vfl + 2);
                mma16816(o[2 * np + 1], al, vfh + 2);
            }
        }
        __syncthreads();
    }

    // ---- finalize + write X hi/lo in (b,l,e) layout ----
    const float inv0 = 1.0f / lr[0], inv1 = 1.0f / lr[1];
    const int b = bh >> 4, h = bh & 15;
    const size_t row0 = (size_t)(b * 1024 + i0 + w * 16 + grp);
    const size_t row1 = row0 + 8;
    #pragma unroll
    for (int nd = 0; nd < 8; ++nd) {
        const int col = h * 64 + nd * 8 + tig * 2;
        uint32_t hi, lo;
        pack_hl(o[nd][0] * inv0, o[nd][1] * inv0, hi, lo);
        *(uint32_t*)&g_Xhi[row0 * 1024 + col] = hi;
        *(uint32_t*)&g_Xlo[row0 * 1024 + col] = lo;
        pack_hl(o[nd][2] * inv1, o[nd][3] * inv1, hi, lo);
        *(uint32_t*)&g_Xhi[row1 * 1024 + col] = hi;
        *(uint32_t*)&g_Xlo[row1 * 1024 + col] = lo;
    }
}

// ---------------------------------------------------------------------------
extern "C" void kernel_launch(void* const* d_in, const int* in_sizes, int n_in,
                              void* d_out, int out_size)
{
    const float* q  = (const float*)d_in[0];
    const float* w3 = (const float*)d_in[1];
    const float* b3 = (const float*)d_in[2];
    const float* ow = (const float*)d_in[3];
    const float* ob = (const float*)d_in[4];
    const float* pe = (const float*)d_in[5];
    float* out = (float*)d_out;

    cudaFuncSetAttribute(attn_mma, cudaFuncAttributeMaxDynamicSharedMemorySize,
                         ATTN_SMEM);
    cudaFuncSetAttribute(mma_gemm<0>, cudaFuncAttributeMaxDynamicSharedMemorySize,
                         GEMM_SMEM);
    cudaFuncSetAttribute(mma_gemm<1>, cudaFuncAttributeMaxDynamicSharedMemorySize,
                         GEMM_SMEM);

    split_kernel<<<4096, 256>>>(q,  4096 * 1024 / 4, 0);
    split_kernel<<<3072, 256>>>(w3, 3072 * 1024 / 4, 1);
    split_kernel<<<1024, 256>>>(ow, 1024 * 1024 / 4, 2);

    mma_gemm<0><<<dim3(24, 32), 256, GEMM_SMEM>>>(b3, nullptr);
    bias_gemm<<<2048, 256>>>(pe);
    attn_mma<<<dim3(8, 64), 256, ATTN_SMEM>>>();
    mma_gemm<1><<<dim3(8, 32), 256, GEMM_SMEM>>>(ob, out);
}

// round 11
// speedup vs baseline: 2.0537x; 1.0041x over previous
#include <cuda_runtime.h>
#include <cuda_bf16.h>
#include <cstdint>

// ---------------------------------------------------------------------------
// RelativeSelfAttention: B=4, L=1024, E=1024, H=16, D=64, K=64 (129 PE rows)
// R11: R9 attention (3-term PV restored) + merged split kernel so that
//      attn_mma sits at ncu's capture index (launch 3).
// ---------------------------------------------------------------------------

#define NBH   64
#define BSTR  132

__device__ float g_Q[NBH * 1024 * 64];          // scaled fp32 Q (for bias_gemm)
__device__ float g_bias[NBH * 1024 * BSTR];

__device__ __nv_bfloat16 g_Ahi[4096 * 1024], g_Alo[4096 * 1024];
__device__ __nv_bfloat16 g_Whi[3072 * 1024], g_Wlo[3072 * 1024];
__device__ __nv_bfloat16 g_OWhi[1024 * 1024], g_OWlo[1024 * 1024];
__device__ __nv_bfloat16 g_Xhi[4096 * 1024], g_Xlo[4096 * 1024];
__device__ __nv_bfloat16 g_Qhi[NBH * 65536], g_Qlo[NBH * 65536];
__device__ __nv_bfloat16 g_Khi[NBH * 65536], g_Klo[NBH * 65536];
__device__ __nv_bfloat16 g_Vhi[NBH * 65536], g_Vlo[NBH * 65536];

// ------------------------------- PTX helpers -------------------------------
__device__ __forceinline__ uint32_t s2u(const void* p) {
    return (uint32_t)__cvta_generic_to_shared(p);
}
__device__ __forceinline__ void ldsm_x4(uint32_t* r, uint32_t addr) {
    asm volatile("ldmatrix.sync.aligned.m8n8.x4.shared.b16 {%0,%1,%2,%3}, [%4];"
        : "=r"(r[0]), "=r"(r[1]), "=r"(r[2]), "=r"(r[3]) : "r"(addr));
}
__device__ __forceinline__ void ldsm_x4_t(uint32_t* r, uint32_t addr) {
    asm volatile("ldmatrix.sync.aligned.m8n8.x4.trans.shared.b16 {%0,%1,%2,%3}, [%4];"
        : "=r"(r[0]), "=r"(r[1]), "=r"(r[2]), "=r"(r[3]) : "r"(addr));
}
__device__ __forceinline__ void mma16816(float* c, const uint32_t* a,
                                         const uint32_t* b) {
    asm volatile(
        "mma.sync.aligned.m16n8k16.row.col.f32.bf16.bf16.f32 "
        "{%0,%1,%2,%3}, {%4,%5,%6,%7}, {%8,%9}, {%0,%1,%2,%3};"
        : "+f"(c[0]), "+f"(c[1]), "+f"(c[2]), "+f"(c[3])
        : "r"(a[0]), "r"(a[1]), "r"(a[2]), "r"(a[3]), "r"(b[0]), "r"(b[1]));
}
__device__ __forceinline__ void cpa16(uint32_t dst, const void* src) {
    asm volatile("cp.async.cg.shared.global [%0], [%1], 16;"
                 :: "r"(dst), "l"(src) : "memory");
}
__device__ __forceinline__ void cpa_commit() {
    asm volatile("cp.async.commit_group;" ::: "memory");
}
template <int N>
__device__ __forceinline__ void cpa_wait() {
    asm volatile("cp.async.wait_group %0;" :: "n"(N) : "memory");
}
__device__ __forceinline__ void pack_hl(float v0, float v1,
                                        uint32_t& hi, uint32_t& lo) {
    __nv_bfloat16 h0 = __float2bfloat16(v0), h1 = __float2bfloat16(v1);
    float l0 = v0 - __bfloat162float(h0), l1 = v1 - __bfloat162float(h1);
    __nv_bfloat162 H; H.x = h0; H.y = h1;
    __nv_bfloat162 L; L.x = __float2bfloat16(l0); L.y = __float2bfloat16(l1);
    hi = *(uint32_t*)&H; lo = *(uint32_t*)&L;
}
__device__ __forceinline__ void split2(__nv_bfloat16* hp, __nv_bfloat16* lp,
                                       size_t idx, float v0, float v1) {
    uint32_t hi, lo;
    pack_hl(v0, v1, hi, lo);
    *(uint32_t*)&hp[idx] = hi;
    *(uint32_t*)&lp[idx] = lo;
}

// ---------------------------------------------------------------------------
// Merged fp32 -> bf16 hi/lo split for q, W3, out_w (single launch).
// ---------------------------------------------------------------------------
__global__ __launch_bounds__(256) void split_all(
    const float* __restrict__ q, const float* __restrict__ w3,
    const float* __restrict__ ow)
{
    int i = blockIdx.x * 256 + threadIdx.x;
    const float* src;
    __nv_bfloat16 *hp, *lp;
    int off;
    if (i < 1048576)      { src = q;  hp = g_Ahi;  lp = g_Alo;  off = i; }
    else if (i < 1835008) { src = w3; hp = g_Whi;  lp = g_Wlo;  off = i - 1048576; }
    else                  { src = ow; hp = g_OWhi; lp = g_OWlo; off = i - 1835008; }
    float4 v = ((const float4*)src)[off];
    __nv_bfloat16 h[4], l[4];
    float f[4] = {v.x, v.y, v.z, v.w};
    #pragma unroll
    for (int k = 0; k < 4; ++k) {
        h[k] = __float2bfloat16(f[k]);
        l[k] = __float2bfloat16(f[k] - __bfloat162float(h[k]));
    }
    *(uint2*)&hp[(size_t)off * 4] = *(uint2*)h;
    *(uint2*)&lp[(size_t)off * 4] = *(uint2*)l;
}

// ---------------------------------------------------------------------------
// Split-bf16 mma.sync GEMM, cp.async double-buffered, 2 CTAs/SM.
// ---------------------------------------------------------------------------
#define SPAD 40
#define ARR_B 10240
#define STG_B (4 * ARR_B)
#define GEMM_SMEM (2 * STG_B)

template <int MODE>
__global__ __launch_bounds__(256, 2) void mma_gemm(
    const float* __restrict__ bias, float* __restrict__ outp)
{
    extern __shared__ __align__(16) char gsm[];
    const uint32_t u0 = s2u(gsm);

    const __nv_bfloat16* Ah = (MODE == 0) ? g_Ahi : g_Xhi;
    const __nv_bfloat16* Al = (MODE == 0) ? g_Alo : g_Xlo;
    const __nv_bfloat16* Bh = (MODE == 0) ? g_Whi : g_OWhi;
    const __nv_bfloat16* Bl = (MODE == 0) ? g_Wlo : g_OWlo;

    const int m0 = blockIdx.y << 7;
    const int n0 = blockIdx.x << 7;
    const int tid = threadIdx.x;
    const int wid = tid >> 5, lane = tid & 31;
    const int wm = wid >> 2, wn = wid & 3;
    const int grp = lane >> 2, tig = lane & 3;

    const int lrow0 = tid >> 2,        lc40 = tid & 3;
    const int lrow1 = (tid + 256) >> 2, lc41 = (tid + 256) & 3;
    const uint32_t sb0 = (uint32_t)(lrow0 * SPAD + lc40 * 8) * 2;
    const uint32_t sb1 = (uint32_t)(lrow1 * SPAD + lc41 * 8) * 2;

    const uint32_t aBase = (uint32_t)(((wm * 64) + (lane & 15)) * SPAD +
                                      (lane >> 4) * 8) * 2;
    const uint32_t bBase = (uint32_t)(((wn * 32) + (lane & 7)) * SPAD +
                                      ((lane >> 3) & 1) * 8) * 2;

    float acc[4][4][4] = {};

    auto issue = [&](int stage, int kc) {
        const int ko = kc * 4;
        const size_t ga0 = (size_t)(m0 + lrow0) * 128 + ko + lc40;
        const size_t ga1 = (size_t)(m0 + lrow1) * 128 + ko + lc41;
        const size_t gb0 = (size_t)(n0 + lrow0) * 128 + ko + lc40;
        const size_t gb1 = (size_t)(n0 + lrow1) * 128 + ko + lc41;
        const uint32_t s = u0 + (uint32_t)stage * STG_B;
        cpa16(s + sb0,             (const uint4*)Ah + ga0);
        cpa16(s + sb1,             (const uint4*)Ah + ga1);
        cpa16(s + ARR_B + sb0,     (const uint4*)Al + ga0);
        cpa16(s + ARR_B + sb1,     (const uint4*)Al + ga1);
        cpa16(s + 2 * ARR_B + sb0, (const uint4*)Bh + gb0);
        cpa16(s + 2 * ARR_B + sb1, (const uint4*)Bh + gb1);
        cpa16(s + 3 * ARR_B + sb0, (const uint4*)Bl + gb0);
        cpa16(s + 3 * ARR_B + sb1, (const uint4*)Bl + gb1);
        cpa_commit();
    };

    issue(0, 0);
    issue(1, 1);

    for (int kc = 0; kc < 32; ++kc) {
        cpa_wait<1>();
        __syncthreads();

        const uint32_t uAh = u0 + (uint32_t)(kc & 1) * STG_B;
        const uint32_t uAl = uAh + ARR_B;
        const uint32_t uBh = uAl + ARR_B;
        const uint32_t uBl = uBh + ARR_B;

        #pragma unroll
        for (int ks = 0; ks < 2; ++ks) {
            const uint32_t kb = (uint32_t)(ks * 16) * 2;
            uint32_t fbh[4][2], fbl[4][2];
            #pragma unroll
            for (int ni = 0; ni < 4; ++ni) {
                uint32_t off = bBase + kb + (uint32_t)(ni * 8 * SPAD) * 2;
                asm volatile("ldmatrix.sync.aligned.m8n8.x2.shared.b16 {%0,%1}, [%2];"
                    : "=r"(fbh[ni][0]), "=r"(fbh[ni][1]) : "r"(uBh + off));
                asm volatile("ldmatrix.sync.aligned.m8n8.x2.shared.b16 {%0,%1}, [%2];"
                    : "=r"(fbl[ni][0]), "=r"(fbl[ni][1]) : "r"(uBl + off));
            }
            #pragma unroll
            for (int mi = 0; mi < 4; ++mi) {
                uint32_t fah[4], fal[4];
                uint32_t off = aBase + kb + (uint32_t)(mi * 16 * SPAD) * 2;
                ldsm_x4(fah, uAh + off);
                ldsm_x4(fal, uAl + off);
                #pragma unroll
                for (int ni = 0; ni < 4; ++ni) {
                    mma16816(acc[mi][ni], fah, fbh[ni]);
                    mma16816(acc[mi][ni], fah, fbl[ni]);
                    mma16816(acc[mi][ni], fal, fbh[ni]);
                }
            }
        }
        __syncthreads();
        if (kc + 2 < 32) issue(kc & 1, kc + 2);
    }

    #pragma unroll
    for (int mi = 0; mi < 4; ++mi) {
        #pragma unroll
        for (int ni = 0; ni < 4; ++ni) {
            const int col = n0 + wn * 32 + ni * 8 + tig * 2;
            const float bv0 = bias[col], bv1 = bias[col + 1];
            #pragma unroll
            for (int rh = 0; rh < 2; ++rh) {
                const int row = m0 + wm * 64 + mi * 16 + grp + rh * 8;
                float v0 = acc[mi][ni][rh * 2 + 0] + bv0;
                float v1 = acc[mi][ni][rh * 2 + 1] + bv1;
                if (MODE == 0) {
                    const int part = col >> 10;
                    const int h = (col & 1023) >> 6;
                    const int d = col & 63;
                    const int b = row >> 10, l = row & 1023;
                    size_t idx = ((size_t)((b << 4) + h) * 1024 + l) * 64 + d;
                    if (part == 0) {
                        v0 *= 0.125f; v1 *= 0.125f;
                        float2 o = {v0, v1};
                        *(float2*)&g_Q[idx] = o;
                        split2(g_Qhi, g_Qlo, idx, v0, v1);
                    } else if (part == 1) {
                        split2(g_Khi, g_Klo, idx, v0, v1);
                    } else {
                        split2(g_Vhi, g_Vlo, idx, v0, v1);
                    }
                } else {
                    float2 o = {v0, v1};
                    *(float2*)&outp[row * 1024 + col] = o;
                }
            }
        }
    }
}

// ---------------------------------------------------------------------------
// Stage 2: bias_r[row, r] = g_Q[row,:] . rel_pe[r,:]
// ---------------------------------------------------------------------------
__global__ __launch_bounds__(256) void bias_gemm(const float* __restrict__ pe)
{
    __shared__ float pes[129 * 64];
    __shared__ float qs[32 * 64];
    const int tid = threadIdx.x;
    const int row0 = blockIdx.x << 5;
    for (int i = tid; i < 129 * 64; i += 256) pes[i] = pe[i];
    for (int i = tid; i < 32 * 64; i += 256) qs[i] = g_Q[row0 * 64 + i];
    __syncthreads();
    for (int idx = tid; idx < 32 * 129; idx += 256) {
        int r = idx / 129, c = idx - r * 129;
        float s = 0.f;
        #pragma unroll
        for (int d = 0; d < 64; d += 4) {
            float4 a = *(const float4*)&qs[(r << 6) + d];
            float4 p = *(const float4*)&pes[(c << 6) + d];
            s = fmaf(a.x, p.x, s); s = fmaf(a.y, p.y, s);
            s = fmaf(a.z, p.z, s); s = fmaf(a.w, p.w, s);
        }
        g_bias[(row0 + r) * BSTR + c] = s;
    }
}

// ---------------------------------------------------------------------------
// Stage 3: flash attention, mma.sync split-bf16 (S and PV both 3-term).
// Band-constant bias + L2 gather; Q resident in smem; 2-stage K/V cp.async.
// ---------------------------------------------------------------------------
#define AT_SPAD 72
#define AT_ARR_B (64 * AT_SPAD * 2)       // 9216 per 64-row array
#define AT_STG_B (4 * AT_ARR_B)           // 36864 per stage (Kh,Kl,Vh,Vl)
#define AT_Q_B   (128 * AT_SPAD * 2)      // 18432 per Q array
#define ATTN_SMEM (2 * AT_STG_B + 2 * AT_Q_B)
#define NJT 16

__global__ __launch_bounds__(256, 2) void attn_mma()
{
    extern __shared__ __align__(16) char smem_raw[];
    const uint32_t u0 = s2u(smem_raw);
    const uint32_t uQh = u0 + 2 * AT_STG_B;
    const uint32_t uQl = uQh + AT_Q_B;

    const int bh = blockIdx.y;
    const int i0 = blockIdx.x << 7;
    const int tid = threadIdx.x;
    const int w = tid >> 5, lane = tid & 31;
    const int grp = lane >> 2, tig = lane & 3;

    const uint4* gKh = (const uint4*)(g_Khi + (size_t)bh * 65536);
    const uint4* gKl = (const uint4*)(g_Klo + (size_t)bh * 65536);
    const uint4* gVh = (const uint4*)(g_Vhi + (size_t)bh * 65536);
    const uint4* gVl = (const uint4*)(g_Vlo + (size_t)bh * 65536);

    const int cr = tid >> 2;
    const int cc = (tid & 3) * 2;
    const uint32_t cdst = (uint32_t)(cr * AT_SPAD * 2) + (uint32_t)cc * 16;
    auto issue_kv = [&](int jt) {
        const uint32_t s = u0 + (uint32_t)(jt & 1) * AT_STG_B;
        const uint4* kh = gKh + jt * 512 + cr * 8 + cc;
        const uint4* kl = gKl + jt * 512 + cr * 8 + cc;
        const uint4* vh = gVh + jt * 512 + cr * 8 + cc;
        const uint4* vl = gVl + jt * 512 + cr * 8 + cc;
        cpa16(s + cdst, kh);                    cpa16(s + cdst + 16, kh + 1);
        cpa16(s + AT_ARR_B + cdst, kl);         cpa16(s + AT_ARR_B + cdst + 16, kl + 1);
        cpa16(s + 2 * AT_ARR_B + cdst, vh);     cpa16(s + 2 * AT_ARR_B + cdst + 16, vh + 1);
        cpa16(s + 3 * AT_ARR_B + cdst, vl);     cpa16(s + 3 * AT_ARR_B + cdst + 16, vl + 1);
        cpa_commit();
    };

    issue_kv(0);

    // stage Q hi/lo into resident smem
    {
        const size_t qbase = (size_t)bh * 65536 + (size_t)i0 * 64;
        const uint4* srcH = (const uint4*)(g_Qhi + qbase);
        const uint4* srcL = (const uint4*)(g_Qlo + qbase);
        __nv_bfloat16* tQh = (__nv_bfloat16*)(smem_raw + 2 * AT_STG_B);
        __nv_bfloat16* tQl = tQh + 128 * AT_SPAD;
        #pragma unroll
        for (int k = 0; k < 4; ++k) {
            int u = tid + k * 256;
            int r = u >> 3, c = (u & 7) * 8;
            *(uint4*)&tQh[r * AT_SPAD + c] = srcH[u];
            *(uint4*)&tQl[r * AT_SPAD + c] = srcL[u];
        }
    }

    // per-row bias pointers + out-of-band constants
    const int r0g = i0 + w * 16 + grp;
    const int r1g = r0g + 8;
    const float* browG0 = g_bias + (size_t)(bh * 1024 + r0g) * BSTR + 64;
    const float* browG1 = g_bias + (size_t)(bh * 1024 + r1g) * BSTR + 64;
    const float clo0 = __ldg(browG0 - 64), chi0 = __ldg(browG0 + 64);
    const float clo1 = __ldg(browG1 - 64), chi1 = __ldg(browG1 + 64);

    float mr[2] = {-1e30f, -1e30f};
    float lr[2] = {0.f, 0.f};
    float o[8][4] = {};

    const uint32_t qro = (uint32_t)((w * 16 + (lane & 15)) * AT_SPAD +
                                    (lane >> 4) * 8) * 2;

    for (int jt = 0; jt < NJT; ++jt) {
        if (jt + 1 < NJT) issue_kv(jt + 1);
        if (jt + 1 < NJT) cpa_wait<1>(); else cpa_wait<0>();
        __syncthreads();

        const uint32_t uKh = u0 + (uint32_t)(jt & 1) * AT_STG_B;
        const uint32_t uKl = uKh + AT_ARR_B;
        const uint32_t uVh = uKl + AT_ARR_B;
        const uint32_t uVl = uVh + AT_ARR_B;
        const int j0 = jt << 6;

        // ---- S = Q K^T (3 terms) ----
        float s[8][4];
        #pragma unroll
        for (int jb = 0; jb < 8; ++jb)
            #pragma unroll
            for (int e = 0; e < 4; ++e) s[jb][e] = 0.f;

        #pragma unroll
        for (int ks = 0; ks < 4; ++ks) {
            uint32_t qh[4], ql[4];
            ldsm_x4(qh, uQh + qro + ks * 32);
            ldsm_x4(ql, uQl + qro + ks * 32);
            #pragma unroll
            for (int jp = 0; jp < 4; ++jp) {
                uint32_t kfh[4], kfl[4];
                uint32_t off = (uint32_t)((jp * 16 + (lane & 7) +
                                           ((lane >> 4) << 3)) * AT_SPAD +
                                          ks * 16 + ((lane >> 3) & 1) * 8) * 2;
                ldsm_x4(kfh, uKh + off);
                ldsm_x4(kfl, uKl + off);
                mma16816(s[2 * jp],     qh, kfh);
                mma16816(s[2 * jp],     qh, kfl);
                mma16816(s[2 * jp],     ql, kfh);
                mma16816(s[2 * jp + 1], qh, kfh + 2);
                mma16816(s[2 * jp + 1], qh, kfl + 2);
                mma16816(s[2 * jp + 1], ql, kfh + 2);
            }
        }

        // ---- relative-PE bias: band-constant or L2 gather ----
        if (j0 + 63 - r0g <= -64) {
            #pragma unroll
            for (int jb = 0; jb < 8; ++jb) { s[jb][0] += clo0; s[jb][1] += clo0; }
        } else if (j0 - r0g >= 64) {
            #pragma unroll
            for (int jb = 0; jb < 8; ++jb) { s[jb][0] += chi0; s[jb][1] += chi0; }
        } else {
            const int dbase0 = j0 + tig * 2 - r0g;
            #pragma unroll
            for (int jb = 0; jb < 8; ++jb) {
                int dA = min(max(dbase0 + jb * 8,     -64), 64);
                int dB = min(max(dbase0 + jb * 8 + 1, -64), 64);
                s[jb][0] += __ldg(browG0 + dA);
                s[jb][1] += __ldg(browG0 + dB);
            }
        }
        if (j0 + 63 - r1g <= -64) {
            #pragma unroll
            for (int jb = 0; jb < 8; ++jb) { s[jb][2] += clo1; s[jb][3] += clo1; }
        } else if (j0 - r1g >= 64) {
            #pragma unroll
            for (int jb = 0; jb < 8; ++jb) { s[jb][2] += chi1; s[jb][3] += chi1; }
        } else {
            const int dbase1 = j0 + tig * 2 - r1g;
            #pragma unroll
            for (int jb = 0; jb < 8; ++jb) {
                int dC = min(max(dbase1 + jb * 8,     -64), 64);
                int dD = min(max(dbase1 + jb * 8 + 1, -64), 64);
                s[jb][2] += __ldg(browG1 + dC);
                s[jb][3] += __ldg(browG1 + dD);
            }
        }

        // ---- online softmax ----
        float mx0 = -1e30f, mx1 = -1e30f;
        #pragma unroll
        for (int jb = 0; jb < 8; ++jb) {
            mx0 = fmaxf(mx0, fmaxf(s[jb][0], s[jb][1]));
            mx1 = fmaxf(mx1, fmaxf(s[jb][2], s[jb][3]));
        }
        mx0 = fmaxf(mx0, __shfl_xor_sync(0xffffffffu, mx0, 1));
        mx0 = fmaxf(mx0, __shfl_xor_sync(0xffffffffu, mx0, 2));
        mx1 = fmaxf(mx1, __shfl_xor_sync(0xffffffffu, mx1, 1));
        mx1 = fmaxf(mx1, __shfl_xor_sync(0xffffffffu, mx1, 2));
        float nm0 = fmaxf(mr[0], mx0), nm1 = fmaxf(mr[1], mx1);
        float sc0 = __expf(mr[0] - nm0), sc1 = __expf(mr[1] - nm1);
        float ps0 = 0.f, ps1 = 0.f;
        #pragma unroll
        for (int jb = 0; jb < 8; ++jb) {
            s[jb][0] = __expf(s[jb][0] - nm0);
            s[jb][1] = __expf(s[jb][1] - nm0);
            s[jb][2] = __expf(s[jb][2] - nm1);
            s[jb][3] = __expf(s[jb][3] - nm1);
            ps0 += s[jb][0] + s[jb][1];
            ps1 += s[jb][2] + s[jb][3];
        }
        ps0 += __shfl_xor_sync(0xffffffffu, ps0, 1);
        ps0 += __shfl_xor_sync(0xffffffffu, ps0, 2);
        ps1 += __shfl_xor_sync(0xffffffffu, ps1, 1);
        ps1 += __shfl_xor_sync(0xffffffffu, ps1, 2);
        lr[0] = lr[0] * sc0 + ps0; mr[0] = nm0;
        lr[1] = lr[1] * sc1 + ps1; mr[1] = nm1;
        #pragma unroll
        for (int nd = 0; nd < 8; ++nd) {
            o[nd][0] *= sc0; o[nd][1] *= sc0;
            o[nd][2] *= sc1; o[nd][3] *= sc1;
        }

        // ---- O += P V (3 terms, P packed from registers) ----
        #pragma unroll
        for (int kk = 0; kk < 4; ++kk) {
            uint32_t ah[4], al[4];
            pack_hl(s[2 * kk][0],     s[2 * kk][1],     ah[0], al[0]);
            pack_hl(s[2 * kk][2],     s[2 * kk][3],     ah[1], al[1]);
            pack_hl(s[2 * kk + 1][0], s[2 * kk + 1][1], ah[2], al[2]);
            pack_hl(s[2 * kk + 1][2], s[2 * kk + 1][3], ah[3], al[3]);
            #pragma unroll
            for (int np = 0; np < 4; ++np) {
                uint32_t vfh[4], vfl[4];
                uint32_t off = (uint32_t)((kk * 16 + (lane & 7) +
                                           ((lane >> 3) & 1) * 8) * AT_SPAD +
                                          np * 16 + (lane >> 4) * 8) * 2;
                ldsm_x4_t(vfh, uVh + off);
                ldsm_x4_t(vfl, uVl + off);
                mma16816(o[2 * np],     ah, vfh);
                mma16816(o[2 * np],     ah, vfl);
                mma16816(o[2 * np],     al, vfh);
                mma16816(o[2 * np + 1], ah, vfh + 2);
                mma16816(o[2 * np + 1], ah, vfl + 2);
                mma16816(o[2 * np + 1], al, vfh + 2);
            }
        }
        __syncthreads();
    }

    // ---- finalize + write X hi/lo in (b,l,e) layout ----
    const float inv0 = 1.0f / lr[0], inv1 = 1.0f / lr[1];
    const int b = bh >> 4, h = bh & 15;
    const size_t row0 = (size_t)(b * 1024 + i0 + w * 16 + grp);
    const size_t row1 = row0 + 8;
    #pragma unroll
    for (int nd = 0; nd < 8; ++nd) {
        const int col = h * 64 + nd * 8 + tig * 2;
        uint32_t hi, lo;
        pack_hl(o[nd][0] * inv0, o[nd][1] * inv0, hi, lo);
        *(uint32_t*)&g_Xhi[row0 * 1024 + col] = hi;
        *(uint32_t*)&g_Xlo[row0 * 1024 + col] = lo;
        pack_hl(o[nd][2] * inv1, o[nd][3] * inv1, hi, lo);
        *(uint32_t*)&g_Xhi[row1 * 1024 + col] = hi;
        *(uint32_t*)&g_Xlo[row1 * 1024 + col] = lo;
    }
}

// ---------------------------------------------------------------------------
extern "C" void kernel_launch(void* const* d_in, const int* in_sizes, int n_in,
                              void* d_out, int out_size)
{
    const float* q  = (const float*)d_in[0];
    const float* w3 = (const float*)d_in[1];
    const float* b3 = (const float*)d_in[2];
    const float* ow = (const float*)d_in[3];
    const float* ob = (const float*)d_in[4];
    const float* pe = (const float*)d_in[5];
    float* out = (float*)d_out;

    cudaFuncSetAttribute(attn_mma, cudaFuncAttributeMaxDynamicSharedMemorySize,
                         ATTN_SMEM);
    cudaFuncSetAttribute(mma_gemm<0>, cudaFuncAttributeMaxDynamicSharedMemorySize,
                         GEMM_SMEM);
    cudaFuncSetAttribute(mma_gemm<1>, cudaFuncAttributeMaxDynamicSharedMemorySize,
                         GEMM_SMEM);

    split_all<<<8192, 256>>>(q, w3, ow);                         // launch 0
    mma_gemm<0><<<dim3(24, 32), 256, GEMM_SMEM>>>(b3, nullptr);  // launch 1
    bias_gemm<<<2048, 256>>>(pe);                                // launch 2
    attn_mma<<<dim3(8, 64), 256, ATTN_SMEM>>>();                 // launch 3 (ncu)
    mma_gemm<1><<<dim3(8, 32), 256, GEMM_SMEM>>>(ob, out);       // launch 4
}

// round 12
// speedup vs baseline: 3.2315x; 1.5735x over previous
#include <cuda_runtime.h>
#include <cuda_bf16.h>
#include <cstdint>

// ---------------------------------------------------------------------------
// RelativeSelfAttention: B=4, L=1024, E=1024, H=16, D=64, K=64 (129 PE rows)
// R12: bias_gemm rebuilt conflict-free (transposed rel_pe in smem).
//      attn/mma paths unchanged from R11.
// ---------------------------------------------------------------------------

#define NBH   64
#define BSTR  132

__device__ float g_Q[NBH * 1024 * 64];          // scaled fp32 Q (for bias_gemm)
__device__ float g_bias[NBH * 1024 * BSTR];

__device__ __nv_bfloat16 g_Ahi[4096 * 1024], g_Alo[4096 * 1024];
__device__ __nv_bfloat16 g_Whi[3072 * 1024], g_Wlo[3072 * 1024];
__device__ __nv_bfloat16 g_OWhi[1024 * 1024], g_OWlo[1024 * 1024];
__device__ __nv_bfloat16 g_Xhi[4096 * 1024], g_Xlo[4096 * 1024];
__device__ __nv_bfloat16 g_Qhi[NBH * 65536], g_Qlo[NBH * 65536];
__device__ __nv_bfloat16 g_Khi[NBH * 65536], g_Klo[NBH * 65536];
__device__ __nv_bfloat16 g_Vhi[NBH * 65536], g_Vlo[NBH * 65536];

// ------------------------------- PTX helpers -------------------------------
__device__ __forceinline__ uint32_t s2u(const void* p) {
    return (uint32_t)__cvta_generic_to_shared(p);
}
__device__ __forceinline__ void ldsm_x4(uint32_t* r, uint32_t addr) {
    asm volatile("ldmatrix.sync.aligned.m8n8.x4.shared.b16 {%0,%1,%2,%3}, [%4];"
        : "=r"(r[0]), "=r"(r[1]), "=r"(r[2]), "=r"(r[3]) : "r"(addr));
}
__device__ __forceinline__ void ldsm_x4_t(uint32_t* r, uint32_t addr) {
    asm volatile("ldmatrix.sync.aligned.m8n8.x4.trans.shared.b16 {%0,%1,%2,%3}, [%4];"
        : "=r"(r[0]), "=r"(r[1]), "=r"(r[2]), "=r"(r[3]) : "r"(addr));
}
__device__ __forceinline__ void mma16816(float* c, const uint32_t* a,
                                         const uint32_t* b) {
    asm volatile(
        "mma.sync.aligned.m16n8k16.row.col.f32.bf16.bf16.f32 "
        "{%0,%1,%2,%3}, {%4,%5,%6,%7}, {%8,%9}, {%0,%1,%2,%3};"
        : "+f"(c[0]), "+f"(c[1]), "+f"(c[2]), "+f"(c[3])
        : "r"(a[0]), "r"(a[1]), "r"(a[2]), "r"(a[3]), "r"(b[0]), "r"(b[1]));
}
__device__ __forceinline__ void cpa16(uint32_t dst, const void* src) {
    asm volatile("cp.async.cg.shared.global [%0], [%1], 16;"
                 :: "r"(dst), "l"(src) : "memory");
}
__device__ __forceinline__ void cpa_commit() {
    asm volatile("cp.async.commit_group;" ::: "memory");
}
template <int N>
__device__ __forceinline__ void cpa_wait() {
    asm volatile("cp.async.wait_group %0;" :: "n"(N) : "memory");
}
__device__ __forceinline__ void pack_hl(float v0, float v1,
                                        uint32_t& hi, uint32_t& lo) {
    __nv_bfloat16 h0 = __float2bfloat16(v0), h1 = __float2bfloat16(v1);
    float l0 = v0 - __bfloat162float(h0), l1 = v1 - __bfloat162float(h1);
    __nv_bfloat162 H; H.x = h0; H.y = h1;
    __nv_bfloat162 L; L.x = __float2bfloat16(l0); L.y = __float2bfloat16(l1);
    hi = *(uint32_t*)&H; lo = *(uint32_t*)&L;
}
__device__ __forceinline__ void split2(__nv_bfloat16* hp, __nv_bfloat16* lp,
                                       size_t idx, float v0, float v1) {
    uint32_t hi, lo;
    pack_hl(v0, v1, hi, lo);
    *(uint32_t*)&hp[idx] = hi;
    *(uint32_t*)&lp[idx] = lo;
}

// ---------------------------------------------------------------------------
// Merged fp32 -> bf16 hi/lo split for q, W3, out_w (single launch).
// ---------------------------------------------------------------------------
__global__ __launch_bounds__(256) void split_all(
    const float* __restrict__ q, const float* __restrict__ w3,
    const float* __restrict__ ow)
{
    int i = blockIdx.x * 256 + threadIdx.x;
    const float* src;
    __nv_bfloat16 *hp, *lp;
    int off;
    if (i < 1048576)      { src = q;  hp = g_Ahi;  lp = g_Alo;  off = i; }
    else if (i < 1835008) { src = w3; hp = g_Whi;  lp = g_Wlo;  off = i - 1048576; }
    else                  { src = ow; hp = g_OWhi; lp = g_OWlo; off = i - 1835008; }
    float4 v = ((const float4*)src)[off];
    __nv_bfloat16 h[4], l[4];
    float f[4] = {v.x, v.y, v.z, v.w};
    #pragma unroll
    for (int k = 0; k < 4; ++k) {
        h[k] = __float2bfloat16(f[k]);
        l[k] = __float2bfloat16(f[k] - __bfloat162float(h[k]));
    }
    *(uint2*)&hp[(size_t)off * 4] = *(uint2*)h;
    *(uint2*)&lp[(size_t)off * 4] = *(uint2*)l;
}

// ---------------------------------------------------------------------------
// Split-bf16 mma.sync GEMM, cp.async double-buffered, 2 CTAs/SM.
// ---------------------------------------------------------------------------
#define SPAD 40
#define ARR_B 10240
#define STG_B (4 * ARR_B)
#define GEMM_SMEM (2 * STG_B)

template <int MODE>
__global__ __launch_bounds__(256, 2) void mma_gemm(
    const float* __restrict__ bias, float* __restrict__ outp)
{
    extern __shared__ __align__(16) char gsm[];
    const uint32_t u0 = s2u(gsm);

    const __nv_bfloat16* Ah = (MODE == 0) ? g_Ahi : g_Xhi;
    const __nv_bfloat16* Al = (MODE == 0) ? g_Alo : g_Xlo;
    const __nv_bfloat16* Bh = (MODE == 0) ? g_Whi : g_OWhi;
    const __nv_bfloat16* Bl = (MODE == 0) ? g_Wlo : g_OWlo;

    const int m0 = blockIdx.y << 7;
    const int n0 = blockIdx.x << 7;
    const int tid = threadIdx.x;
    const int wid = tid >> 5, lane = tid & 31;
    const int wm = wid >> 2, wn = wid & 3;
    const int grp = lane >> 2, tig = lane & 3;

    const int lrow0 = tid >> 2,        lc40 = tid & 3;
    const int lrow1 = (tid + 256) >> 2, lc41 = (tid + 256) & 3;
    const uint32_t sb0 = (uint32_t)(lrow0 * SPAD + lc40 * 8) * 2;
    const uint32_t sb1 = (uint32_t)(lrow1 * SPAD + lc41 * 8) * 2;

    const uint32_t aBase = (uint32_t)(((wm * 64) + (lane & 15)) * SPAD +
                                      (lane >> 4) * 8) * 2;
    const uint32_t bBase = (uint32_t)(((wn * 32) + (lane & 7)) * SPAD +
                                      ((lane >> 3) & 1) * 8) * 2;

    float acc[4][4][4] = {};

    auto issue = [&](int stage, int kc) {
        const int ko = kc * 4;
        const size_t ga0 = (size_t)(m0 + lrow0) * 128 + ko + lc40;
        const size_t ga1 = (size_t)(m0 + lrow1) * 128 + ko + lc41;
        const size_t gb0 = (size_t)(n0 + lrow0) * 128 + ko + lc40;
        const size_t gb1 = (size_t)(n0 + lrow1) * 128 + ko + lc41;
        const uint32_t s = u0 + (uint32_t)stage * STG_B;
        cpa16(s + sb0,             (const uint4*)Ah + ga0);
        cpa16(s + sb1,             (const uint4*)Ah + ga1);
        cpa16(s + ARR_B + sb0,     (const uint4*)Al + ga0);
        cpa16(s + ARR_B + sb1,     (const uint4*)Al + ga1);
        cpa16(s + 2 * ARR_B + sb0, (const uint4*)Bh + gb0);
        cpa16(s + 2 * ARR_B + sb1, (const uint4*)Bh + gb1);
        cpa16(s + 3 * ARR_B + sb0, (const uint4*)Bl + gb0);
        cpa16(s + 3 * ARR_B + sb1, (const uint4*)Bl + gb1);
        cpa_commit();
    };

    issue(0, 0);
    issue(1, 1);

    for (int kc = 0; kc < 32; ++kc) {
        cpa_wait<1>();
        __syncthreads();

        const uint32_t uAh = u0 + (uint32_t)(kc & 1) * STG_B;
        const uint32_t uAl = uAh + ARR_B;
        const uint32_t uBh = uAl + ARR_B;
        const uint32_t uBl = uBh + ARR_B;

        #pragma unroll
        for (int ks = 0; ks < 2; ++ks) {
            const uint32_t kb = (uint32_t)(ks * 16) * 2;
            uint32_t fbh[4][2], fbl[4][2];
            #pragma unroll
            for (int ni = 0; ni < 4; ++ni) {
                uint32_t off = bBase + kb + (uint32_t)(ni * 8 * SPAD) * 2;
                asm volatile("ldmatrix.sync.aligned.m8n8.x2.shared.b16 {%0,%1}, [%2];"
                    : "=r"(fbh[ni][0]), "=r"(fbh[ni][1]) : "r"(uBh + off));
                asm volatile("ldmatrix.sync.aligned.m8n8.x2.shared.b16 {%0,%1}, [%2];"
                    : "=r"(fbl[ni][0]), "=r"(fbl[ni][1]) : "r"(uBl + off));
            }
            #pragma unroll
            for (int mi = 0; mi < 4; ++mi) {
                uint32_t fah[4], fal[4];
                uint32_t off = aBase + kb + (uint32_t)(mi * 16 * SPAD) * 2;
                ldsm_x4(fah, uAh + off);
                ldsm_x4(fal, uAl + off);
                #pragma unroll
                for (int ni = 0; ni < 4; ++ni) {
                    mma16816(acc[mi][ni], fah, fbh[ni]);
                    mma16816(acc[mi][ni], fah, fbl[ni]);
                    mma16816(acc[mi][ni], fal, fbh[ni]);
                }
            }
        }
        __syncthreads();
        if (kc + 2 < 32) issue(kc & 1, kc + 2);
    }

    #pragma unroll
    for (int mi = 0; mi < 4; ++mi) {
        #pragma unroll
        for (int ni = 0; ni < 4; ++ni) {
            const int col = n0 + wn * 32 + ni * 8 + tig * 2;
            const float bv0 = bias[col], bv1 = bias[col + 1];
            #pragma unroll
            for (int rh = 0; rh < 2; ++rh) {
                const int row = m0 + wm * 64 + mi * 16 + grp + rh * 8;
                float v0 = acc[mi][ni][rh * 2 + 0] + bv0;
                float v1 = acc[mi][ni][rh * 2 + 1] + bv1;
                if (MODE == 0) {
                    const int part = col >> 10;
                    const int h = (col & 1023) >> 6;
                    const int d = col & 63;
                    const int b = row >> 10, l = row & 1023;
                    size_t idx = ((size_t)((b << 4) + h) * 1024 + l) * 64 + d;
                    if (part == 0) {
                        v0 *= 0.125f; v1 *= 0.125f;
                        float2 o = {v0, v1};
                        *(float2*)&g_Q[idx] = o;
                        split2(g_Qhi, g_Qlo, idx, v0, v1);
                    } else if (part == 1) {
                        split2(g_Khi, g_Klo, idx, v0, v1);
                    } else {
                        split2(g_Vhi, g_Vlo, idx, v0, v1);
                    }
                } else {
                    float2 o = {v0, v1};
                    *(float2*)&outp[row * 1024 + col] = o;
                }
            }
        }
    }
}

// ---------------------------------------------------------------------------
// Stage 2: bias_r[row, r] = g_Q[row,:] . rel_pe[r,:]
// R12: rel_pe stored TRANSPOSED in smem (pes_t[d][r], stride 132) so the
// per-lane reads are consecutive words -> conflict-free (old layout had a
// 32-way bank conflict on every load).
// ---------------------------------------------------------------------------
__global__ __launch_bounds__(256) void bias_gemm(const float* __restrict__ pe)
{
    __shared__ float pes_t[64 * 132];   // [d][r], 33.8 KB
    __shared__ float qs[32 * 64];       // 8 KB
    const int tid = threadIdx.x;
    const int row0 = blockIdx.x << 5;
    for (int i = tid; i < 129 * 64; i += 256) {
        int r = i >> 6, d = i & 63;
        pes_t[d * 132 + r] = pe[i];
    }
    for (int i = tid; i < 32 * 64; i += 256) qs[i] = g_Q[row0 * 64 + i];
    __syncthreads();
    for (int idx = tid; idx < 32 * 129; idx += 256) {
        int r = idx / 129, c = idx - r * 129;
        const float* qrow = &qs[r << 6];
        float s = 0.f;
        #pragma unroll
        for (int d = 0; d < 64; ++d)
            s = fmaf(qrow[d], pes_t[d * 132 + c], s);
        g_bias[(size_t)(row0 + r) * BSTR + c] = s;
    }
}

// ---------------------------------------------------------------------------
// Stage 3: flash attention, mma.sync split-bf16 (S and PV both 3-term).
// Band-constant bias + L2 gather; Q resident in smem; 2-stage K/V cp.async.
// (unchanged from R11)
// ---------------------------------------------------------------------------
#define AT_SPAD 72
#define AT_ARR_B (64 * AT_SPAD * 2)
#define AT_STG_B (4 * AT_ARR_B)
#define AT_Q_B   (128 * AT_SPAD * 2)
#define ATTN_SMEM (2 * AT_STG_B + 2 * AT_Q_B)
#define NJT 16

__global__ __launch_bounds__(256, 2) void attn_mma()
{
    extern __shared__ __align__(16) char smem_raw[];
    const uint32_t u0 = s2u(smem_raw);
    const uint32_t uQh = u0 + 2 * AT_STG_B;
    const uint32_t uQl = uQh + AT_Q_B;

    const int bh = blockIdx.y;
    const int i0 = blockIdx.x << 7;
    const int tid = threadIdx.x;
    const int w = tid >> 5, lane = tid & 31;
    const int grp = lane >> 2, tig = lane & 3;

    const uint4* gKh = (const uint4*)(g_Khi + (size_t)bh * 65536);
    const uint4* gKl = (const uint4*)(g_Klo + (size_t)bh * 65536);
    const uint4* gVh = (const uint4*)(g_Vhi + (size_t)bh * 65536);
    const uint4* gVl = (const uint4*)(g_Vlo + (size_t)bh * 65536);

    const int cr = tid >> 2;
    const int cc = (tid & 3) * 2;
    const uint32_t cdst = (uint32_t)(cr * AT_SPAD * 2) + (uint32_t)cc * 16;
    auto issue_kv = [&](int jt) {
        const uint32_t s = u0 + (uint32_t)(jt & 1) * AT_STG_B;
        const uint4* kh = gKh + jt * 512 + cr * 8 + cc;
        const uint4* kl = gKl + jt * 512 + cr * 8 + cc;
        const uint4* vh = gVh + jt * 512 + cr * 8 + cc;
        const uint4* vl = gVl + jt * 512 + cr * 8 + cc;
        cpa16(s + cdst, kh);                    cpa16(s + cdst + 16, kh + 1);
        cpa16(s + AT_ARR_B + cdst, kl);         cpa16(s + AT_ARR_B + cdst + 16, kl + 1);
        cpa16(s + 2 * AT_ARR_B + cdst, vh);     cpa16(s + 2 * AT_ARR_B + cdst + 16, vh + 1);
        cpa16(s + 3 * AT_ARR_B + cdst, vl);     cpa16(s + 3 * AT_ARR_B + cdst + 16, vl + 1);
        cpa_commit();
    };

    issue_kv(0);

    {
        const size_t qbase = (size_t)bh * 65536 + (size_t)i0 * 64;
        const uint4* srcH = (const uint4*)(g_Qhi + qbase);
        const uint4* srcL = (const uint4*)(g_Qlo + qbase);
        __nv_bfloat16* tQh = (__nv_bfloat16*)(smem_raw + 2 * AT_STG_B);
        __nv_bfloat16* tQl = tQh + 128 * AT_SPAD;
        #pragma unroll
        for (int k = 0; k < 4; ++k) {
            int u = tid + k * 256;
            int r = u >> 3, c = (u & 7) * 8;
            *(uint4*)&tQh[r * AT_SPAD + c] = srcH[u];
            *(uint4*)&tQl[r * AT_SPAD + c] = srcL[u];
        }
    }

    const int r0g = i0 + w * 16 + grp;
    const int r1g = r0g + 8;
    const float* browG0 = g_bias + (size_t)(bh * 1024 + r0g) * BSTR + 64;
    const float* browG1 = g_bias + (size_t)(bh * 1024 + r1g) * BSTR + 64;
    const float clo0 = __ldg(browG0 - 64), chi0 = __ldg(browG0 + 64);
    const float clo1 = __ldg(browG1 - 64), chi1 = __ldg(browG1 + 64);

    float mr[2] = {-1e30f, -1e30f};
    float lr[2] = {0.f, 0.f};
    float o[8][4] = {};

    const uint32_t qro = (uint32_t)((w * 16 + (lane & 15)) * AT_SPAD +
                                    (lane >> 4) * 8) * 2;

    for (int jt = 0; jt < NJT; ++jt) {
        if (jt + 1 < NJT) issue_kv(jt + 1);
        if (jt + 1 < NJT) cpa_wait<1>(); else cpa_wait<0>();
        __syncthreads();

        const uint32_t uKh = u0 + (uint32_t)(jt & 1) * AT_STG_B;
        const uint32_t uKl = uKh + AT_ARR_B;
        const uint32_t uVh = uKl + AT_ARR_B;
        const uint32_t uVl = uVh + AT_ARR_B;
        const int j0 = jt << 6;

        float s[8][4];
        #pragma unroll
        for (int jb = 0; jb < 8; ++jb)
            #pragma unroll
            for (int e = 0; e < 4; ++e) s[jb][e] = 0.f;

        #pragma unroll
        for (int ks = 0; ks < 4; ++ks) {
            uint32_t qh[4], ql[4];
            ldsm_x4(qh, uQh + qro + ks * 32);
            ldsm_x4(ql, uQl + qro + ks * 32);
            #pragma unroll
            for (int jp = 0; jp < 4; ++jp) {
                uint32_t kfh[4], kfl[4];
                uint32_t off = (uint32_t)((jp * 16 + (lane & 7) +
                                           ((lane >> 4) << 3)) * AT_SPAD +
                                          ks * 16 + ((lane >> 3) & 1) * 8) * 2;
                ldsm_x4(kfh, uKh + off);
                ldsm_x4(kfl, uKl + off);
                mma16816(s[2 * jp],     qh, kfh);
                mma16816(s[2 * jp],     qh, kfl);
                mma16816(s[2 * jp],     ql, kfh);
                mma16816(s[2 * jp + 1], qh, kfh + 2);
                mma16816(s[2 * jp + 1], qh, kfl + 2);
                mma16816(s[2 * jp + 1], ql, kfh + 2);
            }
        }

        if (j0 + 63 - r0g <= -64) {
            #pragma unroll
            for (int jb = 0; jb < 8; ++jb) { s[jb][0] += clo0; s[jb][1] += clo0; }
        } else if (j0 - r0g >= 64) {
            #pragma unroll
            for (int jb = 0; jb < 8; ++jb) { s[jb][0] += chi0; s[jb][1] += chi0; }
        } else {
            const int dbase0 = j0 + tig * 2 - r0g;
            #pragma unroll
            for (int jb = 0; jb < 8; ++jb) {
                int dA = min(max(dbase0 + jb * 8,     -64), 64);
                int dB = min(max(dbase0 + jb * 8 + 1, -64), 64);
                s[jb][0] += __ldg(browG0 + dA);
                s[jb][1] += __ldg(browG0 + dB);
            }
        }
        if (j0 + 63 - r1g <= -64) {
            #pragma unroll
            for (int jb = 0; jb < 8; ++jb) { s[jb][2] += clo1; s[jb][3] += clo1; }
        } else if (j0 - r1g >= 64) {
            #pragma unroll
            for (int jb = 0; jb < 8; ++jb) { s[jb][2] += chi1; s[jb][3] += chi1; }
        } else {
            const int dbase1 = j0 + tig * 2 - r1g;
            #pragma unroll
            for (int jb = 0; jb < 8; ++jb) {
                int dC = min(max(dbase1 + jb * 8,     -64), 64);
                int dD = min(max(dbase1 + jb * 8 + 1, -64), 64);
                s[jb][2] += __ldg(browG1 + dC);
                s[jb][3] += __ldg(browG1 + dD);
            }
        }

        float mx0 = -1e30f, mx1 = -1e30f;
        #pragma unroll
        for (int jb = 0; jb < 8; ++jb) {
            mx0 = fmaxf(mx0, fmaxf(s[jb][0], s[jb][1]));
            mx1 = fmaxf(mx1, fmaxf(s[jb][2], s[jb][3]));
        }
        mx0 = fmaxf(mx0, __shfl_xor_sync(0xffffffffu, mx0, 1));
        mx0 = fmaxf(mx0, __shfl_xor_sync(0xffffffffu, mx0, 2));
        mx1 = fmaxf(mx1, __shfl_xor_sync(0xffffffffu, mx1, 1));
        mx1 = fmaxf(mx1, __shfl_xor_sync(0xffffffffu, mx1, 2));
        float nm0 = fmaxf(mr[0], mx0), nm1 = fmaxf(mr[1], mx1);
        float sc0 = __expf(mr[0] - nm0), sc1 = __expf(mr[1] - nm1);
        float ps0 = 0.f, ps1 = 0.f;
        #pragma unroll
        for (int jb = 0; jb < 8; ++jb) {
            s[jb][0] = __expf(s[jb][0] - nm0);
            s[jb][1] = __expf(s[jb][1] - nm0);
            s[jb][2] = __expf(s[jb][2] - nm1);
            s[jb][3] = __expf(s[jb][3] - nm1);
            ps0 += s[jb][0] + s[jb][1];
            ps1 += s[jb][2] + s[jb][3];
        }
        ps0 += __shfl_xor_sync(0xffffffffu, ps0, 1);
        ps0 += __shfl_xor_sync(0xffffffffu, ps0, 2);
        ps1 += __shfl_xor_sync(0xffffffffu, ps1, 1);
        ps1 += __shfl_xor_sync(0xffffffffu, ps1, 2);
        lr[0] = lr[0] * sc0 + ps0; mr[0] = nm0;
        lr[1] = lr[1] * sc1 + ps1; mr[1] = nm1;
        #pragma unroll
        for (int nd = 0; nd < 8; ++nd) {
            o[nd][0] *= sc0; o[nd][1] *= sc0;
            o[nd][2] *= sc1; o[nd][3] *= sc1;
        }

        #pragma unroll
        for (int kk = 0; kk < 4; ++kk) {
            uint32_t ah[4], al[4];
            pack_hl(s[2 * kk][0],     s[2 * kk][1],     ah[0], al[0]);
            pack_hl(s[2 * kk][2],     s[2 * kk][3],     ah[1], al[1]);
            pack_hl(s[2 * kk + 1][0], s[2 * kk + 1][1], ah[2], al[2]);
            pack_hl(s[2 * kk + 1][2], s[2 * kk + 1][3], ah[3], al[3]);
            #pragma unroll
            for (int np = 0; np < 4; ++np) {
                uint32_t vfh[4], vfl[4];
                uint32_t off = (uint32_t)((kk * 16 + (lane & 7) +
                                           ((lane >> 3) & 1) * 8) * AT_SPAD +
                                          np * 16 + (lane >> 4) * 8) * 2;
                ldsm_x4_t(vfh, uVh + off);
                ldsm_x4_t(vfl, uVl + off);
                mma16816(o[2 * np],     ah, vfh);
                mma16816(o[2 * np],     ah, vfl);
                mma16816(o[2 * np],     al, vfh);
                mma16816(o[2 * np + 1], ah, vfh + 2);
                mma16816(o[2 * np + 1], ah, vfl + 2);
                mma16816(o[2 * np + 1], al, vfh + 2);
            }
        }
        __syncthreads();
    }

    const float inv0 = 1.0f / lr[0], inv1 = 1.0f / lr[1];
    const int b = bh >> 4, h = bh & 15;
    const size_t row0 = (size_t)(b * 1024 + i0 + w * 16 + grp);
    const size_t row1 = row0 + 8;
    #pragma unroll
    for (int nd = 0; nd < 8; ++nd) {
        const int col = h * 64 + nd * 8 + tig * 2;
        uint32_t hi, lo;
        pack_hl(o[nd][0] * inv0, o[nd][1] * inv0, hi, lo);
        *(uint32_t*)&g_Xhi[row0 * 1024 + col] = hi;
        *(uint32_t*)&g_Xlo[row0 * 1024 + col] = lo;
        pack_hl(o[nd][2] * inv1, o[nd][3] * inv1, hi, lo);
        *(uint32_t*)&g_Xhi[row1 * 1024 + col] = hi;
        *(uint32_t*)&g_Xlo[row1 * 1024 + col] = lo;
    }
}

// ---------------------------------------------------------------------------
extern "C" void kernel_launch(void* const* d_in, const int* in_sizes, int n_in,
                              void* d_out, int out_size)
{
    const float* q  = (const float*)d_in[0];
    const float* w3 = (const float*)d_in[1];
    const float* b3 = (const float*)d_in[2];
    const float* ow = (const float*)d_in[3];
    const float* ob = (const float*)d_in[4];
    const float* pe = (const float*)d_in[5];
    float* out = (float*)d_out;

    cudaFuncSetAttribute(attn_mma, cudaFuncAttributeMaxDynamicSharedMemorySize,
                         ATTN_SMEM);
    cudaFuncSetAttribute(mma_gemm<0>, cudaFuncAttributeMaxDynamicSharedMemorySize,
                         GEMM_SMEM);
    cudaFuncSetAttribute(mma_gemm<1>, cudaFuncAttributeMaxDynamicSharedMemorySize,
                         GEMM_SMEM);

    split_all<<<8192, 256>>>(q, w3, ow);                         // launch 0
    mma_gemm<0><<<dim3(24, 32), 256, GEMM_SMEM>>>(b3, nullptr);  // launch 1
    bias_gemm<<<2048, 256>>>(pe);                                // launch 2
    attn_mma<<<dim3(8, 64), 256, ATTN_SMEM>>>();                 // launch 3 (ncu)
    mma_gemm<1><<<dim3(8, 32), 256, GEMM_SMEM>>>(ob, out);       // launch 4
}